// round 7
// baseline (speedup 1.0000x reference)
#include <cuda_runtime.h>
#include <cuda_bf16.h>
#include <cstdint>

#define BB 2
#define LL 4096
#define DIN 512
#define HH 8
#define DK 64
#define DV 64
#define DOUT 512

// ---------------------------------------------------------------------------
// Scratch (__device__ globals; no allocations allowed)
// ---------------------------------------------------------------------------
__device__ float g_Gpart[4 * BB * DIN * DIN];     // Gram split-K partials
__device__ float g_G [BB * DIN * DIN];            // G[b]  = x^T x
__device__ float g_P [BB * HH * DK * DIN];        // P[b,h] = Wk^T G
__device__ float g_Mpart[8 * BB * HH * DK * DV];  // step-3 split-K partials
__device__ float g_M2[BB * HH * DK * DV];         // M[b,h] = P Wv
__device__ float g_T2[BB * DIN * (HH * DV)];      // T2cat[b] (512 x 512)
__device__ float g_F [BB * DIN * DOUT];           // F[b] (512 x 512)

// ---------------------------------------------------------------------------
// Tensor-core GEMM via mma.sync.m16n8k16 bf16 (baseline PTX, no 'a' features)
// C[m0..+128, n0..+128] = sum_k opA[m,k] * opB[n,k]
//   T=1 operand: global is [K x dim] row-major -> op[r,k] = Gl[k*ld + base + r]
//   T=0 operand: global is [dim x K] row-major -> op[r,k] = Gl[(base+r)*ld + k]
// 2-term bf16 split per operand (hi/lo); products AhBh + AhBl + AlBh.
// 8 warps: warp (wr=w&3, wc=w>>2) owns rows wr*32..+31, cols wc*64..+63.
// ---------------------------------------------------------------------------
#define KT 32
#define STRIDE 40                        // bf16 elems per smem row (20 banks: conflict-free)
#define TILE_BYTES (128 * STRIDE * 2)    // 10240

// smem byte offsets for the 4 staged matrices
#define S_AH 0
#define S_AL (1 * TILE_BYTES)
#define S_BH (2 * TILE_BYTES)
#define S_BL (3 * TILE_BYTES)

__device__ __forceinline__ uint32_t pack2(__nv_bfloat16 a, __nv_bfloat16 b) {
    return (uint32_t)__bfloat16_as_ushort(a) | ((uint32_t)__bfloat16_as_ushort(b) << 16);
}

// Load a 128 x KT tile from global fp32, split into bf16 hi/lo, store to smem.
template <int T>
__device__ __forceinline__ void load_tile(
    char* sm, int off_h, int off_l,
    const float* __restrict__ Gl, int ld, int base, int kc, int tid)
{
    if (T) {
        // op[r,k] = Gl[(kc+k)*ld + base + r] ; 1024 float4, 4 per thread
#pragma unroll
        for (int p = 0; p < 4; p++) {
            int f = p * 256 + tid;
            int k  = f >> 5;            // 0..31
            int r4 = (f & 31) * 4;      // 0..124
            float4 v = *(const float4*)(Gl + (long)(kc + k) * ld + base + r4);
            float vv[4] = {v.x, v.y, v.z, v.w};
#pragma unroll
            for (int i = 0; i < 4; i++) {
                __nv_bfloat16 h = __float2bfloat16(vv[i]);
                __nv_bfloat16 l = __float2bfloat16(vv[i] - __bfloat162float(h));
                int eo = (r4 + i) * STRIDE + k;
                *(__nv_bfloat16*)(sm + off_h + eo * 2) = h;
                *(__nv_bfloat16*)(sm + off_l + eo * 2) = l;
            }
        }
    } else {
        // op[r,k] = Gl[(base+r)*ld + kc + k] ; rows contiguous in k
#pragma unroll
        for (int p = 0; p < 4; p++) {
            int f = p * 256 + tid;
            int r  = f >> 3;            // 0..127 (8 float4 per row)
            int k4 = (f & 7) * 4;       // 0..28
            float4 v = *(const float4*)(Gl + (long)(base + r) * ld + kc + k4);
            __nv_bfloat16 h0 = __float2bfloat16(v.x), h1 = __float2bfloat16(v.y);
            __nv_bfloat16 h2 = __float2bfloat16(v.z), h3 = __float2bfloat16(v.w);
            __nv_bfloat16 l0 = __float2bfloat16(v.x - __bfloat162float(h0));
            __nv_bfloat16 l1 = __float2bfloat16(v.y - __bfloat162float(h1));
            __nv_bfloat16 l2 = __float2bfloat16(v.z - __bfloat162float(h2));
            __nv_bfloat16 l3 = __float2bfloat16(v.w - __bfloat162float(h3));
            int bo = (r * STRIDE + k4) * 2;            // 8-byte aligned (k4 even*2)
            uint2 hp = make_uint2(pack2(h0, h1), pack2(h2, h3));
            uint2 lp = make_uint2(pack2(l0, l1), pack2(l2, l3));
            *(uint2*)(sm + off_h + bo) = hp;
            *(uint2*)(sm + off_l + bo) = lp;
        }
    }
}

__device__ __forceinline__ void mma16816(float* c, const uint32_t* a,
                                         uint32_t b0, uint32_t b1) {
    asm volatile(
        "mma.sync.aligned.m16n8k16.row.col.f32.bf16.bf16.f32 "
        "{%0,%1,%2,%3}, {%4,%5,%6,%7}, {%8,%9}, {%0,%1,%2,%3};"
        : "+f"(c[0]), "+f"(c[1]), "+f"(c[2]), "+f"(c[3])
        : "r"(a[0]), "r"(a[1]), "r"(a[2]), "r"(a[3]), "r"(b0), "r"(b1));
}

template <int TA, int TB>
__global__ __launch_bounds__(256, 2) void tgemm(
    const float* __restrict__ A, const float* __restrict__ B, float* __restrict__ C,
    int K, int lda, int ldb, int ldc,
    long sAb, long sBb, long sCb, int nsplit, long splitStride)
{
    __shared__ char sm[4 * TILE_BYTES];

    const int tid = threadIdx.x;
    const int w = tid >> 5;
    const int lane = tid & 31;
    const int gid = lane >> 2;     // 0..7
    const int q = lane & 3;        // 0..3
    const int wr = w & 3;          // row block (32 rows)
    const int wc = w >> 2;         // col block (64 cols)

    int z = blockIdx.z;
    const int split = z % nsplit;
    const int b = z / nsplit;
    A += (long)b * sAb;
    B += (long)b * sBb;
    C += (long)b * sCb + (long)split * splitStride;

    const int m0 = blockIdx.y * 128;
    const int n0 = blockIdx.x * 128;
    const int Kc = K / nsplit;
    const int k0 = split * Kc;
    const int nchunks = Kc / KT;

    float c[2][8][4];
#pragma unroll
    for (int mt = 0; mt < 2; mt++)
#pragma unroll
        for (int nt = 0; nt < 8; nt++)
#pragma unroll
            for (int i = 0; i < 4; i++) c[mt][nt][i] = 0.f;

    for (int ch = 0; ch < nchunks; ch++) {
        const int kc = k0 + ch * KT;
        load_tile<TA>(sm, S_AH, S_AL, A, lda, m0, kc, tid);
        load_tile<TB>(sm, S_BH, S_BL, B, ldb, n0, kc, tid);
        __syncthreads();

#pragma unroll
        for (int ks = 0; ks < 2; ks++) {
            const int kb = ks * 16;     // k offset within chunk
#pragma unroll
            for (int pr = 0; pr < 3; pr++) {
                const int pa = (pr == 2) ? S_AL : S_AH;
                const int pb = (pr == 1) ? S_BL : S_BH;

                // A fragments for both 16-row tiles
                uint32_t a[2][4];
#pragma unroll
                for (int mt = 0; mt < 2; mt++) {
                    const int r0 = wr * 32 + mt * 16 + gid;
                    const int cb = kb + q * 2;
                    a[mt][0] = *(const uint32_t*)(sm + pa + (r0 * STRIDE + cb) * 2);
                    a[mt][1] = *(const uint32_t*)(sm + pa + ((r0 + 8) * STRIDE + cb) * 2);
                    a[mt][2] = *(const uint32_t*)(sm + pa + (r0 * STRIDE + cb + 8) * 2);
                    a[mt][3] = *(const uint32_t*)(sm + pa + ((r0 + 8) * STRIDE + cb + 8) * 2);
                }
#pragma unroll
                for (int nt = 0; nt < 8; nt++) {
                    const int nr = wc * 64 + nt * 8 + gid;
                    const int cb = kb + q * 2;
                    uint32_t b0 = *(const uint32_t*)(sm + pb + (nr * STRIDE + cb) * 2);
                    uint32_t b1 = *(const uint32_t*)(sm + pb + (nr * STRIDE + cb + 8) * 2);
                    mma16816(c[0][nt], a[0], b0, b1);
                    mma16816(c[1][nt], a[1], b0, b1);
                }
            }
        }
        __syncthreads();
    }

    // Epilogue: c0,c1 -> row gid; c2,c3 -> row gid+8
#pragma unroll
    for (int mt = 0; mt < 2; mt++) {
        const int r = m0 + wr * 32 + mt * 16 + gid;
#pragma unroll
        for (int nt = 0; nt < 8; nt++) {
            const int col = n0 + wc * 64 + nt * 8 + q * 2;
            *(float2*)(C + (long)r * ldc + col)       = make_float2(c[mt][nt][0], c[mt][nt][1]);
            *(float2*)(C + (long)(r + 8) * ldc + col) = make_float2(c[mt][nt][2], c[mt][nt][3]);
        }
    }
}

// ---------------------------------------------------------------------------
// Small/medium fp32 GEMM: 64x64 tile (middle chain)
// ---------------------------------------------------------------------------
template <int TRANSA>
__global__ __launch_bounds__(256) void gemm64(
    const float* __restrict__ A, const float* __restrict__ B, float* __restrict__ C,
    int M, int N, int K,
    int lda, int ldb, int ldc,
    long sAb, long sAh, long sBb, long sBh, long sCb, long sCh,
    int nh, int nsplit, long splitStride)
{
    int z = blockIdx.z;
    int split = z % nsplit; z /= nsplit;
    int h = z % nh;
    int b = z / nh;
    A += (long)b * sAb + (long)h * sAh;
    B += (long)b * sBb + (long)h * sBh;
    C += (long)b * sCb + (long)h * sCh + (long)split * splitStride;

    const int Kc = K / nsplit;
    const int k0 = split * Kc;

    __shared__ float As[16][64];
    __shared__ float Bs[16][64];

    const int m0 = blockIdx.y * 64;
    const int n0 = blockIdx.x * 64;
    const int tid = threadIdx.x;
    const int tx = tid & 15;
    const int ty = tid >> 4;

    float acc[4][4];
#pragma unroll
    for (int i = 0; i < 4; i++)
#pragma unroll
        for (int j = 0; j < 4; j++) acc[i][j] = 0.f;

    for (int kt = 0; kt < Kc; kt += 16) {
        if (TRANSA) {
            int k  = tid >> 4;
            int m4 = (tid & 15) * 4;
            float4 v = *reinterpret_cast<const float4*>(
                &A[(long)(k0 + kt + k) * lda + m0 + m4]);
            *reinterpret_cast<float4*>(&As[k][m4]) = v;
        } else {
            int m  = tid >> 2;
            int k4 = (tid & 3) * 4;
            float4 v = *reinterpret_cast<const float4*>(
                &A[(long)(m0 + m) * lda + (k0 + kt + k4)]);
            As[k4 + 0][m] = v.x;
            As[k4 + 1][m] = v.y;
            As[k4 + 2][m] = v.z;
            As[k4 + 3][m] = v.w;
        }
        {
            int k  = tid >> 4;
            int n4 = (tid & 15) * 4;
            float4 v = *reinterpret_cast<const float4*>(
                &B[(long)(k0 + kt + k) * ldb + n0 + n4]);
            *reinterpret_cast<float4*>(&Bs[k][n4]) = v;
        }
        __syncthreads();

#pragma unroll
        for (int k = 0; k < 16; k++) {
            float4 a = *reinterpret_cast<const float4*>(&As[k][ty * 4]);
            float4 bb = *reinterpret_cast<const float4*>(&Bs[k][tx * 4]);
            float av[4] = {a.x, a.y, a.z, a.w};
            float bv[4] = {bb.x, bb.y, bb.z, bb.w};
#pragma unroll
            for (int i = 0; i < 4; i++)
#pragma unroll
                for (int j = 0; j < 4; j++)
                    acc[i][j] += av[i] * bv[j];
        }
        __syncthreads();
    }

#pragma unroll
    for (int i = 0; i < 4; i++) {
        int m = m0 + ty * 4 + i;
        float4 v = make_float4(acc[i][0], acc[i][1], acc[i][2], acc[i][3]);
        *reinterpret_cast<float4*>(&C[(long)m * ldc + n0 + tx * 4]) = v;
    }
}

// Deterministic fixed-order reduction of split-K partials
template <int P>
__global__ void reduceP(float* __restrict__ dst, const float* __restrict__ src, int n)
{
    int i = blockIdx.x * 256 + threadIdx.x;
    if (i < n) {
        float s = 0.f;
#pragma unroll
        for (int p = 0; p < P; p++) s += src[(long)p * n + i];
        dst[i] = s;
    }
}

// ---------------------------------------------------------------------------
extern "C" void kernel_launch(void* const* d_in, const int* in_sizes, int n_in,
                              void* d_out, int out_size)
{
    const float* x  = (const float*)d_in[0];
    const float* Wq = (const float*)d_in[1];
    const float* Wk = (const float*)d_in[2];
    const float* Wv = (const float*)d_in[3];
    const float* Wo = (const float*)d_in[4];
    float* out = (float*)d_out;

    float *G, *Gp, *P, *Mp, *M2, *T2, *F;
    cudaGetSymbolAddress((void**)&G,  g_G);
    cudaGetSymbolAddress((void**)&Gp, g_Gpart);
    cudaGetSymbolAddress((void**)&P,  g_P);
    cudaGetSymbolAddress((void**)&Mp, g_Mpart);
    cudaGetSymbolAddress((void**)&M2, g_M2);
    cudaGetSymbolAddress((void**)&T2, g_T2);
    cudaGetSymbolAddress((void**)&F,  g_F);

    const long LD   = (long)LL * DIN;
    const long GS   = (long)DIN * DIN;
    const long WKS  = (long)DIN * DK;
    const long PSH  = (long)DK * DIN;
    const long PSB  = (long)HH * PSH;
    const long MSH  = (long)DK * DV;
    const long MSB  = (long)HH * MSH;

    // 1) G[b] = x[b]^T x[b]  — mma.sync tensor path, split-K=4 -> 128 CTAs
    tgemm<1, 1><<<dim3(4, 4, BB * 4), 256>>>(
        x, x, Gp, LL, DIN, DIN, DIN,
        LD, LD, GS, /*nsplit=*/4, /*splitStride=*/(long)BB * GS);
    reduceP<4><<<(BB * DIN * DIN + 255) / 256, 256>>>(G, Gp, BB * DIN * DIN);

    // 2) P[b,h] = Wk[h]^T @ G[b]      (64 x 512, K=512), 128 CTAs
    gemm64<1><<<dim3(8, 1, BB * HH), 256>>>(
        Wk, G, P, DK, DIN, DIN,
        DK, DIN, DIN,
        0, WKS, GS, 0, PSB, PSH,
        HH, 1, 0);

    // 3) M[b,h] = P[b,h] @ Wv[h]      (64 x 64, K=512), split-K=8 -> 128 CTAs
    gemm64<0><<<dim3(1, 1, BB * HH * 8), 256>>>(
        P, Wv, Mp, DK, DV, DIN,
        DIN, DV, DV,
        PSB, PSH, 0, WKS, MSB, MSH,
        HH, /*nsplit=*/8, /*splitStride=*/(long)BB * HH * DK * DV);
    reduceP<8><<<(BB * HH * DK * DV + 255) / 256, 256>>>(M2, Mp, BB * HH * DK * DV);

    // 4) T2cat[b][:, h*64:(h+1)*64] = Wq[h] @ M[b,h]   (512 x 64, K=64), 128 CTAs
    gemm64<0><<<dim3(1, 8, BB * HH), 256>>>(
        Wq, M2, T2, DIN, DV, DK,
        DK, DV, HH * DV,
        0, WKS, MSB, MSH, (long)DIN * HH * DV, (long)DV,
        HH, 1, 0);

    // 5) F[b] = T2cat[b] @ Wo_flat    (512 x 512, K=512), 128 CTAs
    gemm64<0><<<dim3(8, 8, BB), 256>>>(
        T2, Wo, F, DIN, DOUT, HH * DV,
        HH * DV, DOUT, DOUT,
        (long)DIN * HH * DV, 0, 0, 0, (long)DIN * DOUT, 0,
        1, 1, 0);

    // 6) out[b] = x[b] @ F[b]  — mma.sync tensor path (A direct, B=F transposed)
    tgemm<0, 1><<<dim3(4, 32, BB), 256>>>(
        x, F, out, DIN, DIN, DOUT, DOUT,
        LD, (long)DIN * DOUT, (long)LL * DOUT, 1, 0);
}

// round 8
// speedup vs baseline: 1.8140x; 1.8140x over previous
#include <cuda_runtime.h>
#include <cuda_bf16.h>
#include <cstdint>

#define BB 2
#define LL 4096
#define DIN 512
#define HH 8
#define DK 64
#define DV 64
#define DOUT 512

// ---------------------------------------------------------------------------
// Scratch (__device__ globals; no allocations allowed)
// ---------------------------------------------------------------------------
__device__ float g_Gpart[4 * BB * DIN * DIN];     // Gram split-K partials
__device__ float g_G [BB * DIN * DIN];            // G[b]  = x^T x
__device__ float g_P [BB * HH * DK * DIN];        // P[b,h] = Wk^T G
__device__ float g_Mpart[8 * BB * HH * DK * DV];  // step-3 split-K partials
__device__ float g_M2[BB * HH * DK * DV];         // M[b,h] = P Wv
__device__ float g_T2[BB * DIN * (HH * DV)];      // T2cat[b] (512 x 512)
__device__ float g_F [BB * DIN * DOUT];           // F[b] (512 x 512)

// bf16 hi/lo split arrays (precomputed once per launch)
__device__ __nv_bfloat16 g_xh [BB * LL * DIN];    // x direct  [b][l][d]
__device__ __nv_bfloat16 g_xl [BB * LL * DIN];
__device__ __nv_bfloat16 g_xTh[BB * DIN * LL];    // x^T       [b][d][l]
__device__ __nv_bfloat16 g_xTl[BB * DIN * LL];
__device__ __nv_bfloat16 g_FTh[BB * DOUT * DIN];  // F^T       [b][o][d]
__device__ __nv_bfloat16 g_FTl[BB * DOUT * DIN];

// ---------------------------------------------------------------------------
// Helpers
// ---------------------------------------------------------------------------
__device__ __forceinline__ uint32_t smem_u32(const void* p) {
    uint32_t a;
    asm("{ .reg .u64 t; cvta.to.shared.u64 t, %1; cvt.u32.u64 %0, t; }" : "=r"(a) : "l"(p));
    return a;
}
__device__ __forceinline__ void cp_async16(uint32_t saddr, const void* gptr) {
    asm volatile("cp.async.ca.shared.global [%0], [%1], 16;" :: "r"(saddr), "l"(gptr));
}
__device__ __forceinline__ void ldm4(uint32_t* r, uint32_t addr) {
    asm volatile("ldmatrix.sync.aligned.m8n8.x4.shared.b16 {%0,%1,%2,%3}, [%4];"
        : "=r"(r[0]), "=r"(r[1]), "=r"(r[2]), "=r"(r[3]) : "r"(addr));
}
__device__ __forceinline__ void mma16816(float* c, const uint32_t* a,
                                         uint32_t b0, uint32_t b1) {
    asm volatile(
        "mma.sync.aligned.m16n8k16.row.col.f32.bf16.bf16.f32 "
        "{%0,%1,%2,%3}, {%4,%5,%6,%7}, {%8,%9}, {%0,%1,%2,%3};"
        : "+f"(c[0]), "+f"(c[1]), "+f"(c[2]), "+f"(c[3])
        : "r"(a[0]), "r"(a[1]), "r"(a[2]), "r"(a[3]), "r"(b0), "r"(b1));
}

// ---------------------------------------------------------------------------
// Split kernels: fp32 -> bf16 hi/lo (+ transpose variants)
// ---------------------------------------------------------------------------
__global__ __launch_bounds__(256) void split_x_kernel(
    const float* __restrict__ x,
    __nv_bfloat16* __restrict__ xh, __nv_bfloat16* __restrict__ xl,
    __nv_bfloat16* __restrict__ xTh, __nv_bfloat16* __restrict__ xTl)
{
    __shared__ float tile[32][33];
    const int tx = threadIdx.x, ty = threadIdx.y;
    const int b = blockIdx.z, d0 = blockIdx.x * 32, l0 = blockIdx.y * 32;
    const float* xb = x + (long)b * LL * DIN;

#pragma unroll
    for (int i = ty; i < 32; i += 8) {
        float v = xb[(long)(l0 + i) * DIN + d0 + tx];
        tile[i][tx] = v;
        __nv_bfloat16 h = __float2bfloat16(v);
        __nv_bfloat16 lo = __float2bfloat16(v - __bfloat162float(h));
        long o = (long)b * LL * DIN + (long)(l0 + i) * DIN + d0 + tx;
        xh[o] = h; xl[o] = lo;
    }
    __syncthreads();
#pragma unroll
    for (int i = ty; i < 32; i += 8) {
        float v = tile[tx][i];      // element (l = l0+tx, d = d0+i)
        __nv_bfloat16 h = __float2bfloat16(v);
        __nv_bfloat16 lo = __float2bfloat16(v - __bfloat162float(h));
        long o = (long)b * DIN * LL + (long)(d0 + i) * LL + l0 + tx;
        xTh[o] = h; xTl[o] = lo;
    }
}

__global__ __launch_bounds__(256) void split_FT_kernel(
    const float* __restrict__ F,
    __nv_bfloat16* __restrict__ FTh, __nv_bfloat16* __restrict__ FTl)
{
    __shared__ float tile[32][33];
    const int tx = threadIdx.x, ty = threadIdx.y;
    const int b = blockIdx.z, o0 = blockIdx.x * 32, d0 = blockIdx.y * 32;
    const float* Fb = F + (long)b * DIN * DOUT;

#pragma unroll
    for (int i = ty; i < 32; i += 8)
        tile[i][tx] = Fb[(long)(d0 + i) * DOUT + o0 + tx];
    __syncthreads();
#pragma unroll
    for (int i = ty; i < 32; i += 8) {
        float v = tile[tx][i];      // element (d = d0+tx, o = o0+i)
        __nv_bfloat16 h = __float2bfloat16(v);
        __nv_bfloat16 lo = __float2bfloat16(v - __bfloat162float(h));
        long o = (long)b * DOUT * DIN + (long)(o0 + i) * DIN + d0 + tx;
        FTh[o] = h; FTl[o] = lo;
    }
}

// ---------------------------------------------------------------------------
// bf16 tensor GEMM: C[128x128 fp32] = sum_k A[m,k]*B[n,k]
// A, B given as hi/lo bf16 pairs, both [row][k] row-major.
// Products: AhBh + AhBl + AlBh (fp32 accum).
// 256 threads (8 warps: wr=w&3 rows, wc=w>>2 cols), KT=32 chunks,
// cp.async double-buffered smem, ldmatrix fragments.
// ---------------------------------------------------------------------------
#define KT 32
#define STRIDE 40                        // bf16 per smem row -> conflict-free ldmatrix
#define TILE_B (128 * STRIDE * 2)        // 10240 bytes
#define S_AH 0
#define S_AL (1 * TILE_B)
#define S_BH (2 * TILE_B)
#define S_BL (3 * TILE_B)
#define BUF_B (4 * TILE_B)               // 40960
#define TG_SMEM (2 * BUF_B)              // 81920

__global__ __launch_bounds__(256, 2) void tgemm_bf16(
    const __nv_bfloat16* __restrict__ Ah, const __nv_bfloat16* __restrict__ Al,
    const __nv_bfloat16* __restrict__ Bh, const __nv_bfloat16* __restrict__ Bl,
    float* __restrict__ C,
    int K, int lda, int ldb, int ldc,
    long sAb, long sBb, long sCb, int nsplit, long splitStride)
{
    extern __shared__ char sm[];
    const uint32_t sb = smem_u32(sm);

    const int tid = threadIdx.x;
    const int w = tid >> 5;
    const int lane = tid & 31;
    const int gid = lane >> 2;
    const int q = lane & 3;
    const int wr = w & 3;
    const int wc = w >> 2;

    int z = blockIdx.z;
    const int split = z % nsplit;
    const int b = z / nsplit;
    Ah += (long)b * sAb; Al += (long)b * sAb;
    Bh += (long)b * sBb; Bl += (long)b * sBb;
    C += (long)b * sCb + (long)split * splitStride;

    const int m0 = blockIdx.y * 128;
    const int n0 = blockIdx.x * 128;
    const int Kc = K / nsplit;
    const int k0 = split * Kc;
    const int nchunks = Kc / KT;

    // per-thread load slots: 2 segments per tile (512 uint4 / 256 thr)
    const int r1 = tid >> 2,           s1 = tid & 3;
    const int r2 = (tid + 256) >> 2,   s2 = (tid + 256) & 3;

    float c[2][8][4];
#pragma unroll
    for (int mt = 0; mt < 2; mt++)
#pragma unroll
        for (int nt = 0; nt < 8; nt++)
#pragma unroll
            for (int i = 0; i < 4; i++) c[mt][nt][i] = 0.f;

    // issue cp.async for one chunk into buffer `buf`
    auto issue = [&](int ch, int buf) {
        const int kc = k0 + ch * KT;
        const uint32_t base = sb + buf * BUF_B;
        const __nv_bfloat16* gp[4] = {Ah, Al, Bh, Bl};
        const int off[4] = {S_AH, S_AL, S_BH, S_BL};
#pragma unroll
        for (int t = 0; t < 4; t++) {
            const int ld = (t < 2) ? lda : ldb;
            const int rb = (t < 2) ? m0 : n0;
            cp_async16(base + off[t] + (r1 * STRIDE + s1 * 8) * 2,
                       gp[t] + (long)(rb + r1) * ld + kc + s1 * 8);
            cp_async16(base + off[t] + (r2 * STRIDE + s2 * 8) * 2,
                       gp[t] + (long)(rb + r2) * ld + kc + s2 * 8);
        }
        asm volatile("cp.async.commit_group;" ::: "memory");
    };

    issue(0, 0);

    // ldmatrix lane address offsets (shared by A and B)
    const int lrow = (lane & 7) + ((lane >> 3) & 1) * 8;
    const int lcol = (lane >> 4) * 8;

    for (int ch = 0; ch < nchunks; ch++) {
        const int cur = ch & 1;
        if (ch + 1 < nchunks) {
            issue(ch + 1, cur ^ 1);
            asm volatile("cp.async.wait_group 1;" ::: "memory");
        } else {
            asm volatile("cp.async.wait_group 0;" ::: "memory");
        }
        __syncthreads();

        const uint32_t base = sb + cur * BUF_B;
#pragma unroll
        for (int ks = 0; ks < 2; ks++) {
            const int kb = ks * 16;
#pragma unroll
            for (int pr = 0; pr < 3; pr++) {
                const uint32_t pa = base + ((pr == 2) ? S_AL : S_AH);
                const uint32_t pb = base + ((pr == 1) ? S_BL : S_BH);

                uint32_t a[2][4];
#pragma unroll
                for (int mt = 0; mt < 2; mt++) {
                    const int row = wr * 32 + mt * 16 + lrow;
                    ldm4(a[mt], pa + (row * STRIDE + kb + lcol) * 2);
                }
#pragma unroll
                for (int ng = 0; ng < 4; ng++) {
                    const int row = wc * 64 + ng * 16 + lrow;
                    uint32_t bm[4];
                    ldm4(bm, pb + (row * STRIDE + kb + lcol) * 2);
                    // bm[0]=b0(nt=2ng) bm[1]=b0(2ng+1) bm[2]=b1(2ng) bm[3]=b1(2ng+1)
                    mma16816(c[0][ng * 2],     a[0], bm[0], bm[2]);
                    mma16816(c[0][ng * 2 + 1], a[0], bm[1], bm[3]);
                    mma16816(c[1][ng * 2],     a[1], bm[0], bm[2]);
                    mma16816(c[1][ng * 2 + 1], a[1], bm[1], bm[3]);
                }
            }
        }
        __syncthreads();
    }

    // Epilogue
#pragma unroll
    for (int mt = 0; mt < 2; mt++) {
        const int r = m0 + wr * 32 + mt * 16 + gid;
#pragma unroll
        for (int nt = 0; nt < 8; nt++) {
            const int col = n0 + wc * 64 + nt * 8 + q * 2;
            *(float2*)(C + (long)r * ldc + col)       = make_float2(c[mt][nt][0], c[mt][nt][1]);
            *(float2*)(C + (long)(r + 8) * ldc + col) = make_float2(c[mt][nt][2], c[mt][nt][3]);
        }
    }
}

// ---------------------------------------------------------------------------
// Small/medium fp32 GEMM: 64x64 tile (middle chain) — unchanged, passing
// ---------------------------------------------------------------------------
template <int TRANSA>
__global__ __launch_bounds__(256) void gemm64(
    const float* __restrict__ A, const float* __restrict__ B, float* __restrict__ C,
    int M, int N, int K,
    int lda, int ldb, int ldc,
    long sAb, long sAh, long sBb, long sBh, long sCb, long sCh,
    int nh, int nsplit, long splitStride)
{
    int z = blockIdx.z;
    int split = z % nsplit; z /= nsplit;
    int h = z % nh;
    int b = z / nh;
    A += (long)b * sAb + (long)h * sAh;
    B += (long)b * sBb + (long)h * sBh;
    C += (long)b * sCb + (long)h * sCh + (long)split * splitStride;

    const int Kc = K / nsplit;
    const int k0 = split * Kc;

    __shared__ float As[16][64];
    __shared__ float Bs[16][64];

    const int m0 = blockIdx.y * 64;
    const int n0 = blockIdx.x * 64;
    const int tid = threadIdx.x;
    const int tx = tid & 15;
    const int ty = tid >> 4;

    float acc[4][4];
#pragma unroll
    for (int i = 0; i < 4; i++)
#pragma unroll
        for (int j = 0; j < 4; j++) acc[i][j] = 0.f;

    for (int kt = 0; kt < Kc; kt += 16) {
        if (TRANSA) {
            int k  = tid >> 4;
            int m4 = (tid & 15) * 4;
            float4 v = *reinterpret_cast<const float4*>(
                &A[(long)(k0 + kt + k) * lda + m0 + m4]);
            *reinterpret_cast<float4*>(&As[k][m4]) = v;
        } else {
            int m  = tid >> 2;
            int k4 = (tid & 3) * 4;
            float4 v = *reinterpret_cast<const float4*>(
                &A[(long)(m0 + m) * lda + (k0 + kt + k4)]);
            As[k4 + 0][m] = v.x;
            As[k4 + 1][m] = v.y;
            As[k4 + 2][m] = v.z;
            As[k4 + 3][m] = v.w;
        }
        {
            int k  = tid >> 4;
            int n4 = (tid & 15) * 4;
            float4 v = *reinterpret_cast<const float4*>(
                &B[(long)(k0 + kt + k) * ldb + n0 + n4]);
            *reinterpret_cast<float4*>(&Bs[k][n4]) = v;
        }
        __syncthreads();

#pragma unroll
        for (int k = 0; k < 16; k++) {
            float4 a = *reinterpret_cast<const float4*>(&As[k][ty * 4]);
            float4 bb = *reinterpret_cast<const float4*>(&Bs[k][tx * 4]);
            float av[4] = {a.x, a.y, a.z, a.w};
            float bv[4] = {bb.x, bb.y, bb.z, bb.w};
#pragma unroll
            for (int i = 0; i < 4; i++)
#pragma unroll
                for (int j = 0; j < 4; j++)
                    acc[i][j] += av[i] * bv[j];
        }
        __syncthreads();
    }

#pragma unroll
    for (int i = 0; i < 4; i++) {
        int m = m0 + ty * 4 + i;
        float4 v = make_float4(acc[i][0], acc[i][1], acc[i][2], acc[i][3]);
        *reinterpret_cast<float4*>(&C[(long)m * ldc + n0 + tx * 4]) = v;
    }
}

// Deterministic fixed-order reduction of split-K partials
template <int P>
__global__ void reduceP(float* __restrict__ dst, const float* __restrict__ src, int n)
{
    int i = blockIdx.x * 256 + threadIdx.x;
    if (i < n) {
        float s = 0.f;
#pragma unroll
        for (int p = 0; p < P; p++) s += src[(long)p * n + i];
        dst[i] = s;
    }
}

// ---------------------------------------------------------------------------
extern "C" void kernel_launch(void* const* d_in, const int* in_sizes, int n_in,
                              void* d_out, int out_size)
{
    const float* x  = (const float*)d_in[0];
    const float* Wq = (const float*)d_in[1];
    const float* Wk = (const float*)d_in[2];
    const float* Wv = (const float*)d_in[3];
    const float* Wo = (const float*)d_in[4];
    float* out = (float*)d_out;

    float *G, *Gp, *P, *Mp, *M2, *T2, *F;
    cudaGetSymbolAddress((void**)&G,  g_G);
    cudaGetSymbolAddress((void**)&Gp, g_Gpart);
    cudaGetSymbolAddress((void**)&P,  g_P);
    cudaGetSymbolAddress((void**)&Mp, g_Mpart);
    cudaGetSymbolAddress((void**)&M2, g_M2);
    cudaGetSymbolAddress((void**)&T2, g_T2);
    cudaGetSymbolAddress((void**)&F,  g_F);

    __nv_bfloat16 *xh, *xl, *xTh, *xTl, *FTh, *FTl;
    cudaGetSymbolAddress((void**)&xh,  g_xh);
    cudaGetSymbolAddress((void**)&xl,  g_xl);
    cudaGetSymbolAddress((void**)&xTh, g_xTh);
    cudaGetSymbolAddress((void**)&xTl, g_xTl);
    cudaGetSymbolAddress((void**)&FTh, g_FTh);
    cudaGetSymbolAddress((void**)&FTl, g_FTl);

    cudaFuncSetAttribute(tgemm_bf16, cudaFuncAttributeMaxDynamicSharedMemorySize, TG_SMEM);

    const long LD   = (long)LL * DIN;
    const long GS   = (long)DIN * DIN;
    const long WKS  = (long)DIN * DK;
    const long PSH  = (long)DK * DIN;
    const long PSB  = (long)HH * PSH;
    const long MSH  = (long)DK * DV;
    const long MSB  = (long)HH * MSH;

    // 0) split x into bf16 hi/lo (direct + transposed)
    split_x_kernel<<<dim3(DIN / 32, LL / 32, BB), dim3(32, 8)>>>(x, xh, xl, xTh, xTl);

    // 1) G[b] = x^T x — bf16 tensor path on xT [b][d][l], split-K=4 -> 128 CTAs
    tgemm_bf16<<<dim3(4, 4, BB * 4), 256, TG_SMEM>>>(
        xTh, xTl, xTh, xTl, Gp,
        LL, LL, LL, DIN,
        (long)DIN * LL, (long)DIN * LL, GS,
        /*nsplit=*/4, /*splitStride=*/(long)BB * GS);
    reduceP<4><<<(BB * DIN * DIN + 255) / 256, 256>>>(G, Gp, BB * DIN * DIN);

    // 2) P[b,h] = Wk[h]^T @ G[b]      (64 x 512, K=512), 128 CTAs
    gemm64<1><<<dim3(8, 1, BB * HH), 256>>>(
        Wk, G, P, DK, DIN, DIN,
        DK, DIN, DIN,
        0, WKS, GS, 0, PSB, PSH,
        HH, 1, 0);

    // 3) M[b,h] = P[b,h] @ Wv[h]      (64 x 64, K=512), split-K=8 -> 128 CTAs
    gemm64<0><<<dim3(1, 1, BB * HH * 8), 256>>>(
        P, Wv, Mp, DK, DV, DIN,
        DIN, DV, DV,
        PSB, PSH, 0, WKS, MSB, MSH,
        HH, /*nsplit=*/8, /*splitStride=*/(long)BB * HH * DK * DV);
    reduceP<8><<<(BB * HH * DK * DV + 255) / 256, 256>>>(M2, Mp, BB * HH * DK * DV);

    // 4) T2cat[b][:, h*64:(h+1)*64] = Wq[h] @ M[b,h]   (512 x 64, K=64), 128 CTAs
    gemm64<0><<<dim3(1, 8, BB * HH), 256>>>(
        Wq, M2, T2, DIN, DV, DK,
        DK, DV, HH * DV,
        0, WKS, MSB, MSH, (long)DIN * HH * DV, (long)DV,
        HH, 1, 0);

    // 5) F[b] = T2cat[b] @ Wo_flat    (512 x 512, K=512), 128 CTAs
    gemm64<0><<<dim3(8, 8, BB), 256>>>(
        T2, Wo, F, DIN, DOUT, HH * DV,
        HH * DV, DOUT, DOUT,
        (long)DIN * HH * DV, 0, 0, 0, (long)DIN * DOUT, 0,
        1, 1, 0);

    // 5b) split F^T into bf16 hi/lo
    split_FT_kernel<<<dim3(DOUT / 32, DIN / 32, BB), dim3(32, 8)>>>(F, FTh, FTl);

    // 6) out[b] = x[b] @ F[b] — bf16 tensor path (A=x direct, B=F^T), 256 CTAs
    tgemm_bf16<<<dim3(4, 32, BB), 256, TG_SMEM>>>(
        xh, xl, FTh, FTl, out,
        DIN, DIN, DIN, DOUT,
        LD, (long)DOUT * DIN, (long)LL * DOUT,
        /*nsplit=*/1, 0);
}

// round 9
// speedup vs baseline: 1.8265x; 1.0069x over previous
#include <cuda_runtime.h>
#include <cuda_bf16.h>
#include <cstdint>

#define BB 2
#define LL 4096
#define DIN 512
#define HH 8
#define DK 64
#define DV 64
#define DOUT 512

// ---------------------------------------------------------------------------
// Scratch (__device__ globals; no allocations allowed)
// ---------------------------------------------------------------------------
__device__ float g_Gp1[4 * BB * DIN * DIN];       // Gram partials: Xh^T Xh
__device__ float g_Gp2[4 * BB * DIN * DIN];       // Gram partials: Xh^T Xl
__device__ float g_P [BB * HH * DK * DIN];        // P_all[b] (512x512)
__device__ float g_Mpart[8 * BB * HH * DK * DV];  // step-3 split-K partials
__device__ float g_M2[BB * HH * DK * DV];         // M[b,h] = P Wv
__device__ float g_T2[BB * DIN * (HH * DV)];      // T2cat[b] (512 x 512)
__device__ float g_F [BB * DIN * DOUT];           // F[b] (512 x 512)

// bf16 hi/lo split arrays
__device__ __nv_bfloat16 g_xh [BB * LL * DIN];    // x direct  [b][l][d]
__device__ __nv_bfloat16 g_xl [BB * LL * DIN];
__device__ __nv_bfloat16 g_xTh[BB * DIN * LL];    // x^T       [b][d][l]
__device__ __nv_bfloat16 g_xTl[BB * DIN * LL];
__device__ __nv_bfloat16 g_FTh[BB * DOUT * DIN];  // F^T       [b][o][d]
__device__ __nv_bfloat16 g_FTl[BB * DOUT * DIN];
__device__ __nv_bfloat16 g_Gh [BB * DIN * DIN];   // G bf16 hi (symmetric)
__device__ __nv_bfloat16 g_Gl [BB * DIN * DIN];   // G bf16 lo
__device__ __nv_bfloat16 g_WkTh[HH * DK * DIN];   // WkT flat: row h*64+k, col d
__device__ __nv_bfloat16 g_WkTl[HH * DK * DIN];

// ---------------------------------------------------------------------------
// Helpers
// ---------------------------------------------------------------------------
__device__ __forceinline__ uint32_t smem_u32(const void* p) {
    uint32_t a;
    asm("{ .reg .u64 t; cvta.to.shared.u64 t, %1; cvt.u32.u64 %0, t; }" : "=r"(a) : "l"(p));
    return a;
}
__device__ __forceinline__ void cp_async16(uint32_t saddr, const void* gptr) {
    asm volatile("cp.async.ca.shared.global [%0], [%1], 16;" :: "r"(saddr), "l"(gptr));
}
__device__ __forceinline__ void ldm4(uint32_t* r, uint32_t addr) {
    asm volatile("ldmatrix.sync.aligned.m8n8.x4.shared.b16 {%0,%1,%2,%3}, [%4];"
        : "=r"(r[0]), "=r"(r[1]), "=r"(r[2]), "=r"(r[3]) : "r"(addr));
}
__device__ __forceinline__ void mma16816(float* c, const uint32_t* a,
                                         uint32_t b0, uint32_t b1) {
    asm volatile(
        "mma.sync.aligned.m16n8k16.row.col.f32.bf16.bf16.f32 "
        "{%0,%1,%2,%3}, {%4,%5,%6,%7}, {%8,%9}, {%0,%1,%2,%3};"
        : "+f"(c[0]), "+f"(c[1]), "+f"(c[2]), "+f"(c[3])
        : "r"(a[0]), "r"(a[1]), "r"(a[2]), "r"(a[3]), "r"(b0), "r"(b1));
}
__device__ __forceinline__ void bf16split(float v, __nv_bfloat16& h, __nv_bfloat16& l) {
    h = __float2bfloat16(v);
    l = __float2bfloat16(v - __bfloat162float(h));
}

// ---------------------------------------------------------------------------
// Split / prep kernels
// ---------------------------------------------------------------------------
__global__ __launch_bounds__(256) void split_x_kernel(
    const float* __restrict__ x,
    __nv_bfloat16* __restrict__ xh, __nv_bfloat16* __restrict__ xl,
    __nv_bfloat16* __restrict__ xTh, __nv_bfloat16* __restrict__ xTl)
{
    __shared__ float tile[32][33];
    const int tx = threadIdx.x, ty = threadIdx.y;
    const int b = blockIdx.z, d0 = blockIdx.x * 32, l0 = blockIdx.y * 32;
    const float* xb = x + (long)b * LL * DIN;

#pragma unroll
    for (int i = ty; i < 32; i += 8) {
        float v = xb[(long)(l0 + i) * DIN + d0 + tx];
        tile[i][tx] = v;
        __nv_bfloat16 h, lo; bf16split(v, h, lo);
        long o = (long)b * LL * DIN + (long)(l0 + i) * DIN + d0 + tx;
        xh[o] = h; xl[o] = lo;
    }
    __syncthreads();
#pragma unroll
    for (int i = ty; i < 32; i += 8) {
        float v = tile[tx][i];
        __nv_bfloat16 h, lo; bf16split(v, h, lo);
        long o = (long)b * DIN * LL + (long)(d0 + i) * LL + l0 + tx;
        xTh[o] = h; xTl[o] = lo;
    }
}

__global__ __launch_bounds__(256) void split_FT_kernel(
    const float* __restrict__ F,
    __nv_bfloat16* __restrict__ FTh, __nv_bfloat16* __restrict__ FTl)
{
    __shared__ float tile[32][33];
    const int tx = threadIdx.x, ty = threadIdx.y;
    const int b = blockIdx.z, o0 = blockIdx.x * 32, d0 = blockIdx.y * 32;
    const float* Fb = F + (long)b * DIN * DOUT;

#pragma unroll
    for (int i = ty; i < 32; i += 8)
        tile[i][tx] = Fb[(long)(d0 + i) * DOUT + o0 + tx];
    __syncthreads();
#pragma unroll
    for (int i = ty; i < 32; i += 8) {
        float v = tile[tx][i];
        __nv_bfloat16 h, lo; bf16split(v, h, lo);
        long o = (long)b * DOUT * DIN + (long)(o0 + i) * DIN + d0 + tx;
        FTh[o] = h; FTl[o] = lo;
    }
}

// WkT[h*64+k][d] = Wk[h][d][k], bf16 hi/lo
__global__ __launch_bounds__(256) void prep_WkT_kernel(
    const float* __restrict__ Wk,
    __nv_bfloat16* __restrict__ WkTh, __nv_bfloat16* __restrict__ WkTl)
{
    __shared__ float tile[32][33];
    const int tx = threadIdx.x, ty = threadIdx.y;
    const int h = blockIdx.z, k0 = blockIdx.x * 32, d0 = blockIdx.y * 32;
    const float* W = Wk + (long)h * DIN * DK;

#pragma unroll
    for (int r = ty; r < 32; r += 8)
        tile[r][tx] = W[(long)(d0 + r) * DK + k0 + tx];   // tile[d-off][k-off]
    __syncthreads();
#pragma unroll
    for (int ii = ty; ii < 32; ii += 8) {
        float v = tile[tx][ii];                            // Wk[h][d0+tx][k0+ii]
        __nv_bfloat16 hh, lo; bf16split(v, hh, lo);
        long o = (long)(h * DK + k0 + ii) * DIN + d0 + tx;
        WkTh[o] = hh; WkTl[o] = lo;
    }
}

// G = sum_p Gp1 + sum_p Gp2 + (sum_p Gp2)^T ; emit bf16 hi/lo
__global__ __launch_bounds__(256) void reduceG_kernel(
    const float* __restrict__ Gp1, const float* __restrict__ Gp2,
    __nv_bfloat16* __restrict__ Gh, __nv_bfloat16* __restrict__ Gl)
{
    __shared__ float T[32][33];
    const int tx = threadIdx.x, ty = threadIdx.y;
    const int b = blockIdx.z, j0 = blockIdx.x * 32, i0 = blockIdx.y * 32;
    const long GSL = (long)DIN * DIN;
    const long PS = (long)BB * GSL;

    // transposed tile: T[r][c] = sum_p Gp2[p][b][j0+r][i0+c]
#pragma unroll
    for (int r = ty; r < 32; r += 8) {
        float s = 0.f;
#pragma unroll
        for (int p = 0; p < 4; p++)
            s += Gp2[p * PS + b * GSL + (long)(j0 + r) * DIN + i0 + tx];
        T[r][tx] = s;
    }
    __syncthreads();
#pragma unroll
    for (int ii = ty; ii < 32; ii += 8) {
        const long ro = (long)(i0 + ii) * DIN + j0 + tx;
        float s = 0.f;
#pragma unroll
        for (int p = 0; p < 4; p++)
            s += Gp1[p * PS + b * GSL + ro] + Gp2[p * PS + b * GSL + ro];
        s += T[tx][ii];
        __nv_bfloat16 h, lo; bf16split(s, h, lo);
        Gh[b * GSL + ro] = h; Gl[b * GSL + ro] = lo;
    }
}

// ---------------------------------------------------------------------------
// bf16 tensor GEMM: C[128x128 fp32] = sum_k A[m,k]*B[n,k]
// PR=3: AhBh + AhBl + AlBh.  PR=1: AhBh only (lo tiles never loaded).
// ---------------------------------------------------------------------------
#define KT 32
#define STRIDE 40
#define TILE_B (128 * STRIDE * 2)
#define S_AH 0
#define S_AL (1 * TILE_B)
#define S_BH (2 * TILE_B)
#define S_BL (3 * TILE_B)
#define BUF_B (4 * TILE_B)
#define TG_SMEM (2 * BUF_B)

template <int PR>
__global__ __launch_bounds__(256, 2) void tgemm_bf16(
    const __nv_bfloat16* __restrict__ Ah, const __nv_bfloat16* __restrict__ Al,
    const __nv_bfloat16* __restrict__ Bh, const __nv_bfloat16* __restrict__ Bl,
    float* __restrict__ C,
    int K, int lda, int ldb, int ldc,
    long sAb, long sBb, long sCb, int nsplit, long splitStride)
{
    extern __shared__ char sm[];
    const uint32_t sb = smem_u32(sm);

    const int tid = threadIdx.x;
    const int w = tid >> 5;
    const int lane = tid & 31;
    const int gid = lane >> 2;
    const int q = lane & 3;
    const int wr = w & 3;
    const int wc = w >> 2;

    int z = blockIdx.z;
    const int split = z % nsplit;
    const int b = z / nsplit;
    Ah += (long)b * sAb; Al += (long)b * sAb;
    Bh += (long)b * sBb; Bl += (long)b * sBb;
    C += (long)b * sCb + (long)split * splitStride;

    const int m0 = blockIdx.y * 128;
    const int n0 = blockIdx.x * 128;
    const int Kc = K / nsplit;
    const int k0 = split * Kc;
    const int nchunks = Kc / KT;

    const int r1 = tid >> 2,           s1 = tid & 3;
    const int r2 = (tid + 256) >> 2,   s2 = (tid + 256) & 3;

    float c[2][8][4];
#pragma unroll
    for (int mt = 0; mt < 2; mt++)
#pragma unroll
        for (int nt = 0; nt < 8; nt++)
#pragma unroll
            for (int i = 0; i < 4; i++) c[mt][nt][i] = 0.f;

    auto issue = [&](int ch, int buf) {
        const int kc = k0 + ch * KT;
        const uint32_t base = sb + buf * BUF_B;
        const __nv_bfloat16* gp[4] = {Ah, Al, Bh, Bl};
        const int off[4] = {S_AH, S_AL, S_BH, S_BL};
#pragma unroll
        for (int t = 0; t < 4; t++) {
            if (PR == 1 && (t & 1)) continue;   // skip lo tiles
            const int ld = (t < 2) ? lda : ldb;
            const int rb = (t < 2) ? m0 : n0;
            cp_async16(base + off[t] + (r1 * STRIDE + s1 * 8) * 2,
                       gp[t] + (long)(rb + r1) * ld + kc + s1 * 8);
            cp_async16(base + off[t] + (r2 * STRIDE + s2 * 8) * 2,
                       gp[t] + (long)(rb + r2) * ld + kc + s2 * 8);
        }
        asm volatile("cp.async.commit_group;" ::: "memory");
    };

    issue(0, 0);

    const int lrow = (lane & 7) + ((lane >> 3) & 1) * 8;
    const int lcol = (lane >> 4) * 8;

    for (int ch = 0; ch < nchunks; ch++) {
        const int cur = ch & 1;
        if (ch + 1 < nchunks) {
            issue(ch + 1, cur ^ 1);
            asm volatile("cp.async.wait_group 1;" ::: "memory");
        } else {
            asm volatile("cp.async.wait_group 0;" ::: "memory");
        }
        __syncthreads();

        const uint32_t base = sb + cur * BUF_B;
#pragma unroll
        for (int ks = 0; ks < 2; ks++) {
            const int kb = ks * 16;
#pragma unroll
            for (int pr = 0; pr < PR; pr++) {
                const uint32_t pa = base + ((pr == 2) ? S_AL : S_AH);
                const uint32_t pb = base + ((pr == 1) ? S_BL : S_BH);

                uint32_t a[2][4];
#pragma unroll
                for (int mt = 0; mt < 2; mt++) {
                    const int row = wr * 32 + mt * 16 + lrow;
                    ldm4(a[mt], pa + (row * STRIDE + kb + lcol) * 2);
                }
#pragma unroll
                for (int ng = 0; ng < 4; ng++) {
                    const int row = wc * 64 + ng * 16 + lrow;
                    uint32_t bm[4];
                    ldm4(bm, pb + (row * STRIDE + kb + lcol) * 2);
                    mma16816(c[0][ng * 2],     a[0], bm[0], bm[2]);
                    mma16816(c[0][ng * 2 + 1], a[0], bm[1], bm[3]);
                    mma16816(c[1][ng * 2],     a[1], bm[0], bm[2]);
                    mma16816(c[1][ng * 2 + 1], a[1], bm[1], bm[3]);
                }
            }
        }
        __syncthreads();
    }

#pragma unroll
    for (int mt = 0; mt < 2; mt++) {
        const int r = m0 + wr * 32 + mt * 16 + gid;
#pragma unroll
        for (int nt = 0; nt < 8; nt++) {
            const int col = n0 + wc * 64 + nt * 8 + q * 2;
            *(float2*)(C + (long)r * ldc + col)       = make_float2(c[mt][nt][0], c[mt][nt][1]);
            *(float2*)(C + (long)(r + 8) * ldc + col) = make_float2(c[mt][nt][2], c[mt][nt][3]);
        }
    }
}

// ---------------------------------------------------------------------------
// Small fp32 GEMM: 64x64 tile (middle chain steps 3-5)
// ---------------------------------------------------------------------------
template <int TRANSA>
__global__ __launch_bounds__(256) void gemm64(
    const float* __restrict__ A, const float* __restrict__ B, float* __restrict__ C,
    int M, int N, int K,
    int lda, int ldb, int ldc,
    long sAb, long sAh, long sBb, long sBh, long sCb, long sCh,
    int nh, int nsplit, long splitStride)
{
    int z = blockIdx.z;
    int split = z % nsplit; z /= nsplit;
    int h = z % nh;
    int b = z / nh;
    A += (long)b * sAb + (long)h * sAh;
    B += (long)b * sBb + (long)h * sBh;
    C += (long)b * sCb + (long)h * sCh + (long)split * splitStride;

    const int Kc = K / nsplit;
    const int k0 = split * Kc;

    __shared__ float As[16][64];
    __shared__ float Bs[16][64];

    const int m0 = blockIdx.y * 64;
    const int n0 = blockIdx.x * 64;
    const int tid = threadIdx.x;
    const int tx = tid & 15;
    const int ty = tid >> 4;

    float acc[4][4];
#pragma unroll
    for (int i = 0; i < 4; i++)
#pragma unroll
        for (int j = 0; j < 4; j++) acc[i][j] = 0.f;

    for (int kt = 0; kt < Kc; kt += 16) {
        if (TRANSA) {
            int k  = tid >> 4;
            int m4 = (tid & 15) * 4;
            float4 v = *reinterpret_cast<const float4*>(
                &A[(long)(k0 + kt + k) * lda + m0 + m4]);
            *reinterpret_cast<float4*>(&As[k][m4]) = v;
        } else {
            int m  = tid >> 2;
            int k4 = (tid & 3) * 4;
            float4 v = *reinterpret_cast<const float4*>(
                &A[(long)(m0 + m) * lda + (k0 + kt + k4)]);
            As[k4 + 0][m] = v.x;
            As[k4 + 1][m] = v.y;
            As[k4 + 2][m] = v.z;
            As[k4 + 3][m] = v.w;
        }
        {
            int k  = tid >> 4;
            int n4 = (tid & 15) * 4;
            float4 v = *reinterpret_cast<const float4*>(
                &B[(long)(k0 + kt + k) * ldb + n0 + n4]);
            *reinterpret_cast<float4*>(&Bs[k][n4]) = v;
        }
        __syncthreads();

#pragma unroll
        for (int k = 0; k < 16; k++) {
            float4 a = *reinterpret_cast<const float4*>(&As[k][ty * 4]);
            float4 bb = *reinterpret_cast<const float4*>(&Bs[k][tx * 4]);
            float av[4] = {a.x, a.y, a.z, a.w};
            float bv[4] = {bb.x, bb.y, bb.z, bb.w};
#pragma unroll
            for (int i = 0; i < 4; i++)
#pragma unroll
                for (int j = 0; j < 4; j++)
                    acc[i][j] += av[i] * bv[j];
        }
        __syncthreads();
    }

#pragma unroll
    for (int i = 0; i < 4; i++) {
        int m = m0 + ty * 4 + i;
        float4 v = make_float4(acc[i][0], acc[i][1], acc[i][2], acc[i][3]);
        *reinterpret_cast<float4*>(&C[(long)m * ldc + n0 + tx * 4]) = v;
    }
}

template <int P>
__global__ void reduceP(float* __restrict__ dst, const float* __restrict__ src, int n)
{
    int i = blockIdx.x * 256 + threadIdx.x;
    if (i < n) {
        float s = 0.f;
#pragma unroll
        for (int p = 0; p < P; p++) s += src[(long)p * n + i];
        dst[i] = s;
    }
}

// ---------------------------------------------------------------------------
extern "C" void kernel_launch(void* const* d_in, const int* in_sizes, int n_in,
                              void* d_out, int out_size)
{
    const float* x  = (const float*)d_in[0];
    const float* Wq = (const float*)d_in[1];
    const float* Wk = (const float*)d_in[2];
    const float* Wv = (const float*)d_in[3];
    const float* Wo = (const float*)d_in[4];
    float* out = (float*)d_out;

    float *Gp1, *Gp2, *P, *Mp, *M2, *T2, *F;
    cudaGetSymbolAddress((void**)&Gp1, g_Gp1);
    cudaGetSymbolAddress((void**)&Gp2, g_Gp2);
    cudaGetSymbolAddress((void**)&P,   g_P);
    cudaGetSymbolAddress((void**)&Mp,  g_Mpart);
    cudaGetSymbolAddress((void**)&M2,  g_M2);
    cudaGetSymbolAddress((void**)&T2,  g_T2);
    cudaGetSymbolAddress((void**)&F,   g_F);

    __nv_bfloat16 *xh, *xl, *xTh, *xTl, *FTh, *FTl, *Gh, *Gl, *WkTh, *WkTl;
    cudaGetSymbolAddress((void**)&xh,   g_xh);
    cudaGetSymbolAddress((void**)&xl,   g_xl);
    cudaGetSymbolAddress((void**)&xTh,  g_xTh);
    cudaGetSymbolAddress((void**)&xTl,  g_xTl);
    cudaGetSymbolAddress((void**)&FTh,  g_FTh);
    cudaGetSymbolAddress((void**)&FTl,  g_FTl);
    cudaGetSymbolAddress((void**)&Gh,   g_Gh);
    cudaGetSymbolAddress((void**)&Gl,   g_Gl);
    cudaGetSymbolAddress((void**)&WkTh, g_WkTh);
    cudaGetSymbolAddress((void**)&WkTl, g_WkTl);

    cudaFuncSetAttribute(tgemm_bf16<3>, cudaFuncAttributeMaxDynamicSharedMemorySize, TG_SMEM);
    cudaFuncSetAttribute(tgemm_bf16<1>, cudaFuncAttributeMaxDynamicSharedMemorySize, TG_SMEM);

    const long LD   = (long)LL * DIN;
    const long GS   = (long)DIN * DIN;
    const long WKS  = (long)DIN * DK;
    const long PSH  = (long)DK * DIN;
    const long PSB  = (long)HH * PSH;      // = GS
    const long MSH  = (long)DK * DV;
    const long MSB  = (long)HH * MSH;
    const long XTS  = (long)DIN * LL;

    // 0) split x (direct + transposed); prep WkT
    split_x_kernel<<<dim3(DIN / 32, LL / 32, BB), dim3(32, 8)>>>(x, xh, xl, xTh, xTl);
    prep_WkT_kernel<<<dim3(DK / 32, DIN / 32, HH), dim3(32, 8)>>>(Wk, WkTh, WkTl);

    // 1) Gram, symmetric 2-product scheme (split-K=4 each -> 128 CTAs)
    //    Gp1 = Xh^T Xh ; Gp2 = Xh^T Xl ; G = Gp1 + Gp2 + Gp2^T
    tgemm_bf16<1><<<dim3(4, 4, BB * 4), 256, TG_SMEM>>>(
        xTh, xTh, xTh, xTh, Gp1,
        LL, LL, LL, DIN, XTS, XTS, GS, 4, (long)BB * GS);
    tgemm_bf16<1><<<dim3(4, 4, BB * 4), 256, TG_SMEM>>>(
        xTh, xTh, xTl, xTl, Gp2,
        LL, LL, LL, DIN, XTS, XTS, GS, 4, (long)BB * GS);
    reduceG_kernel<<<dim3(16, 16, BB), dim3(32, 8)>>>(Gp1, Gp2, Gh, Gl);

    // 2) P_all[b] = WkT_flat @ G[b]  (512x512, K=512; G symmetric -> no transpose)
    tgemm_bf16<3><<<dim3(4, 4, BB), 256, TG_SMEM>>>(
        WkTh, WkTl, Gh, Gl, P,
        DIN, DIN, DIN, DIN, 0, GS, GS, 1, 0);

    // 3) M[b,h] = P[b,h] @ Wv[h]  (64x64, K=512), split-K=8 -> 128 CTAs
    gemm64<0><<<dim3(1, 1, BB * HH * 8), 256>>>(
        P, Wv, Mp, DK, DV, DIN,
        DIN, DV, DV,
        PSB, PSH, 0, WKS, MSB, MSH,
        HH, 8, (long)BB * HH * DK * DV);
    reduceP<8><<<(BB * HH * DK * DV + 255) / 256, 256>>>(M2, Mp, BB * HH * DK * DV);

    // 4) T2cat[b][:, h*64:] = Wq[h] @ M[b,h]  (512x64, K=64), 128 CTAs
    gemm64<0><<<dim3(1, 8, BB * HH), 256>>>(
        Wq, M2, T2, DIN, DV, DK,
        DK, DV, HH * DV,
        0, WKS, MSB, MSH, (long)DIN * HH * DV, (long)DV,
        HH, 1, 0);

    // 5) F[b] = T2cat[b] @ Wo_flat  (512x512, K=512), 128 CTAs
    gemm64<0><<<dim3(8, 8, BB), 256>>>(
        T2, Wo, F, DIN, DOUT, HH * DV,
        HH * DV, DOUT, DOUT,
        (long)DIN * HH * DV, 0, 0, 0, (long)DIN * DOUT, 0,
        1, 1, 0);

    // 5b) split F^T
    split_FT_kernel<<<dim3(DOUT / 32, DIN / 32, BB), dim3(32, 8)>>>(F, FTh, FTl);

    // 6) out[b] = x[b] @ F[b]  (tensor, 3-product), 256 CTAs
    tgemm_bf16<3><<<dim3(4, 32, BB), 256, TG_SMEM>>>(
        xh, xl, FTh, FTl, out,
        DIN, DIN, DIN, DOUT,
        LD, (long)DOUT * DIN, (long)LL * DOUT, 1, 0);
}

// round 10
// speedup vs baseline: 2.1363x; 1.1696x over previous
#include <cuda_runtime.h>
#include <cuda_bf16.h>
#include <cstdint>

#define BB 2
#define LL 4096
#define DIN 512
#define HH 8
#define DK 64
#define DV 64
#define DOUT 512

// ---------------------------------------------------------------------------
// Scratch (__device__ globals; no allocations allowed)
// ---------------------------------------------------------------------------
__device__ float g_Gp1[8 * BB * DIN * DIN];       // Gram partials XhXh / step2 partials
__device__ float g_Gp2[8 * BB * DIN * DIN];       // Gram partials XhXl / step5 partials
__device__ float g_P [BB * HH * DK * DIN];        // P_all[b] (512x512)
__device__ float g_Mpart[8 * BB * HH * DK * DV];  // step-3 split-K partials
__device__ float g_M2[BB * HH * DK * DV];         // M[b,h] = P Wv
__device__ float g_T2[BB * DIN * (HH * DV)];      // T2cat[b] (512 x 512)
__device__ float g_F [BB * DIN * DOUT];           // F[b] (512 x 512)

// bf16 hi/lo split arrays
__device__ __nv_bfloat16 g_xh [BB * LL * DIN];    // x direct  [b][l][d]
__device__ __nv_bfloat16 g_xl [BB * LL * DIN];
__device__ __nv_bfloat16 g_xTh[BB * DIN * LL];    // x^T       [b][d][l]
__device__ __nv_bfloat16 g_xTl[BB * DIN * LL];
__device__ __nv_bfloat16 g_FTh[BB * DOUT * DIN];  // F^T       [b][o][d]
__device__ __nv_bfloat16 g_FTl[BB * DOUT * DIN];
__device__ __nv_bfloat16 g_Gh [BB * DIN * DIN];   // G bf16 hi (symmetric)
__device__ __nv_bfloat16 g_Gl [BB * DIN * DIN];   // G bf16 lo
__device__ __nv_bfloat16 g_WkTh[HH * DK * DIN];   // WkT flat: row h*64+k, col d
__device__ __nv_bfloat16 g_WkTl[HH * DK * DIN];

// ---------------------------------------------------------------------------
// Helpers
// ---------------------------------------------------------------------------
__device__ __forceinline__ uint32_t smem_u32(const void* p) {
    uint32_t a;
    asm("{ .reg .u64 t; cvta.to.shared.u64 t, %1; cvt.u32.u64 %0, t; }" : "=r"(a) : "l"(p));
    return a;
}
__device__ __forceinline__ void cp_async16(uint32_t saddr, const void* gptr) {
    asm volatile("cp.async.ca.shared.global [%0], [%1], 16;" :: "r"(saddr), "l"(gptr));
}
__device__ __forceinline__ void ldm4(uint32_t* r, uint32_t addr) {
    asm volatile("ldmatrix.sync.aligned.m8n8.x4.shared.b16 {%0,%1,%2,%3}, [%4];"
        : "=r"(r[0]), "=r"(r[1]), "=r"(r[2]), "=r"(r[3]) : "r"(addr));
}
__device__ __forceinline__ void mma16816(float* c, const uint32_t* a,
                                         uint32_t b0, uint32_t b1) {
    asm volatile(
        "mma.sync.aligned.m16n8k16.row.col.f32.bf16.bf16.f32 "
        "{%0,%1,%2,%3}, {%4,%5,%6,%7}, {%8,%9}, {%0,%1,%2,%3};"
        : "+f"(c[0]), "+f"(c[1]), "+f"(c[2]), "+f"(c[3])
        : "r"(a[0]), "r"(a[1]), "r"(a[2]), "r"(a[3]), "r"(b0), "r"(b1));
}
__device__ __forceinline__ void bf16split(float v, __nv_bfloat16& h, __nv_bfloat16& l) {
    h = __float2bfloat16(v);
    l = __float2bfloat16(v - __bfloat162float(h));
}

// ---------------------------------------------------------------------------
// Split / prep kernels
// ---------------------------------------------------------------------------
__global__ __launch_bounds__(256) void split_x_kernel(
    const float* __restrict__ x,
    __nv_bfloat16* __restrict__ xh, __nv_bfloat16* __restrict__ xl,
    __nv_bfloat16* __restrict__ xTh, __nv_bfloat16* __restrict__ xTl)
{
    __shared__ float tile[32][33];
    const int tx = threadIdx.x, ty = threadIdx.y;
    const int b = blockIdx.z, d0 = blockIdx.x * 32, l0 = blockIdx.y * 32;
    const float* xb = x + (long)b * LL * DIN;

#pragma unroll
    for (int i = ty; i < 32; i += 8) {
        float v = xb[(long)(l0 + i) * DIN + d0 + tx];
        tile[i][tx] = v;
        __nv_bfloat16 h, lo; bf16split(v, h, lo);
        long o = (long)b * LL * DIN + (long)(l0 + i) * DIN + d0 + tx;
        xh[o] = h; xl[o] = lo;
    }
    __syncthreads();
#pragma unroll
    for (int i = ty; i < 32; i += 8) {
        float v = tile[tx][i];
        __nv_bfloat16 h, lo; bf16split(v, h, lo);
        long o = (long)b * DIN * LL + (long)(d0 + i) * LL + l0 + tx;
        xTh[o] = h; xTl[o] = lo;
    }
}

__global__ __launch_bounds__(256) void split_FT_kernel(
    const float* __restrict__ F,
    __nv_bfloat16* __restrict__ FTh, __nv_bfloat16* __restrict__ FTl)
{
    __shared__ float tile[32][33];
    const int tx = threadIdx.x, ty = threadIdx.y;
    const int b = blockIdx.z, o0 = blockIdx.x * 32, d0 = blockIdx.y * 32;
    const float* Fb = F + (long)b * DIN * DOUT;

#pragma unroll
    for (int i = ty; i < 32; i += 8)
        tile[i][tx] = Fb[(long)(d0 + i) * DOUT + o0 + tx];
    __syncthreads();
#pragma unroll
    for (int i = ty; i < 32; i += 8) {
        float v = tile[tx][i];
        __nv_bfloat16 h, lo; bf16split(v, h, lo);
        long o = (long)b * DOUT * DIN + (long)(o0 + i) * DIN + d0 + tx;
        FTh[o] = h; FTl[o] = lo;
    }
}

// WkT[h*64+k][d] = Wk[h][d][k], bf16 hi/lo
__global__ __launch_bounds__(256) void prep_WkT_kernel(
    const float* __restrict__ Wk,
    __nv_bfloat16* __restrict__ WkTh, __nv_bfloat16* __restrict__ WkTl)
{
    __shared__ float tile[32][33];
    const int tx = threadIdx.x, ty = threadIdx.y;
    const int h = blockIdx.z, k0 = blockIdx.x * 32, d0 = blockIdx.y * 32;
    const float* W = Wk + (long)h * DIN * DK;

#pragma unroll
    for (int r = ty; r < 32; r += 8)
        tile[r][tx] = W[(long)(d0 + r) * DK + k0 + tx];
    __syncthreads();
#pragma unroll
    for (int ii = ty; ii < 32; ii += 8) {
        float v = tile[tx][ii];
        __nv_bfloat16 hh, lo; bf16split(v, hh, lo);
        long o = (long)(h * DK + k0 + ii) * DIN + d0 + tx;
        WkTh[o] = hh; WkTl[o] = lo;
    }
}

// G = sum_p Gp1 + sum_p Gp2 + (sum_p Gp2)^T ; emit bf16 hi/lo  (P=8 partials)
__global__ __launch_bounds__(256) void reduceG_kernel(
    const float* __restrict__ Gp1, const float* __restrict__ Gp2,
    __nv_bfloat16* __restrict__ Gh, __nv_bfloat16* __restrict__ Gl)
{
    __shared__ float T[32][33];
    const int tx = threadIdx.x, ty = threadIdx.y;
    const int b = blockIdx.z, j0 = blockIdx.x * 32, i0 = blockIdx.y * 32;
    const long GSL = (long)DIN * DIN;
    const long PS = (long)BB * GSL;

#pragma unroll
    for (int r = ty; r < 32; r += 8) {
        float s = 0.f;
#pragma unroll
        for (int p = 0; p < 8; p++)
            s += Gp2[p * PS + b * GSL + (long)(j0 + r) * DIN + i0 + tx];
        T[r][tx] = s;
    }
    __syncthreads();
#pragma unroll
    for (int ii = ty; ii < 32; ii += 8) {
        const long ro = (long)(i0 + ii) * DIN + j0 + tx;
        float s = 0.f;
#pragma unroll
        for (int p = 0; p < 8; p++)
            s += Gp1[p * PS + b * GSL + ro] + Gp2[p * PS + b * GSL + ro];
        s += T[tx][ii];
        __nv_bfloat16 h, lo; bf16split(s, h, lo);
        Gh[b * GSL + ro] = h; Gl[b * GSL + ro] = lo;
    }
}

// ---------------------------------------------------------------------------
// bf16 tensor GEMM: C[128x128 fp32] = sum_k A[m,k]*B[n,k]
// PR=3: AhBh + AhBl + AlBh (4 smem tiles/buffer, 80KB).
// PR=1: AhBh only (2 smem tiles/buffer, 40KB -> 2 CTAs/SM).
// ---------------------------------------------------------------------------
#define KT 32
#define STRIDE 40
#define TILE_B (128 * STRIDE * 2)

template <int PR>
__global__ __launch_bounds__(256, 2) void tgemm_bf16(
    const __nv_bfloat16* __restrict__ Ah, const __nv_bfloat16* __restrict__ Al,
    const __nv_bfloat16* __restrict__ Bh, const __nv_bfloat16* __restrict__ Bl,
    float* __restrict__ C,
    int K, int lda, int ldb, int ldc,
    long sAb, long sBb, long sCb, int nsplit, long splitStride)
{
    constexpr int NTILE = (PR == 1) ? 2 : 4;
    constexpr int BUF_B = NTILE * TILE_B;
    constexpr int S_AH = 0;
    constexpr int S_AL = (PR == 1) ? 0 : TILE_B;
    constexpr int S_BH = (PR == 1) ? TILE_B : 2 * TILE_B;
    constexpr int S_BL = (PR == 1) ? TILE_B : 3 * TILE_B;

    extern __shared__ char sm[];
    const uint32_t sb = smem_u32(sm);

    const int tid = threadIdx.x;
    const int w = tid >> 5;
    const int lane = tid & 31;
    const int gid = lane >> 2;
    const int q = lane & 3;
    const int wr = w & 3;
    const int wc = w >> 2;

    int z = blockIdx.z;
    const int split = z % nsplit;
    const int b = z / nsplit;
    Ah += (long)b * sAb; Al += (long)b * sAb;
    Bh += (long)b * sBb; Bl += (long)b * sBb;
    C += (long)b * sCb + (long)split * splitStride;

    const int m0 = blockIdx.y * 128;
    const int n0 = blockIdx.x * 128;
    const int Kc = K / nsplit;
    const int k0 = split * Kc;
    const int nchunks = Kc / KT;

    const int r1 = tid >> 2,           s1 = tid & 3;
    const int r2 = (tid + 256) >> 2,   s2 = (tid + 256) & 3;

    float c[2][8][4];
#pragma unroll
    for (int mt = 0; mt < 2; mt++)
#pragma unroll
        for (int nt = 0; nt < 8; nt++)
#pragma unroll
            for (int i = 0; i < 4; i++) c[mt][nt][i] = 0.f;

    auto issue = [&](int ch, int buf) {
        const int kc = k0 + ch * KT;
        const uint32_t base = sb + buf * BUF_B;
#pragma unroll
        for (int t = 0; t < 4; t++) {
            if (PR == 1 && (t & 1)) continue;   // skip lo tiles
            const __nv_bfloat16* gp = (t == 0) ? Ah : (t == 1) ? Al : (t == 2) ? Bh : Bl;
            const int off = (t == 0) ? S_AH : (t == 1) ? S_AL : (t == 2) ? S_BH : S_BL;
            const int ld = (t < 2) ? lda : ldb;
            const int rb = (t < 2) ? m0 : n0;
            cp_async16(base + off + (r1 * STRIDE + s1 * 8) * 2,
                       gp + (long)(rb + r1) * ld + kc + s1 * 8);
            cp_async16(base + off + (r2 * STRIDE + s2 * 8) * 2,
                       gp + (long)(rb + r2) * ld + kc + s2 * 8);
        }
        asm volatile("cp.async.commit_group;" ::: "memory");
    };

    issue(0, 0);

    const int lrow = (lane & 7) + ((lane >> 3) & 1) * 8;
    const int lcol = (lane >> 4) * 8;

    for (int ch = 0; ch < nchunks; ch++) {
        const int cur = ch & 1;
        if (ch + 1 < nchunks) {
            issue(ch + 1, cur ^ 1);
            asm volatile("cp.async.wait_group 1;" ::: "memory");
        } else {
            asm volatile("cp.async.wait_group 0;" ::: "memory");
        }
        __syncthreads();

        const uint32_t base = sb + cur * BUF_B;
#pragma unroll
        for (int ks = 0; ks < 2; ks++) {
            const int kb = ks * 16;
#pragma unroll
            for (int pr = 0; pr < PR; pr++) {
                const uint32_t pa = base + ((pr == 2) ? S_AL : S_AH);
                const uint32_t pb = base + ((pr == 1) ? S_BL : S_BH);

                uint32_t a[2][4];
#pragma unroll
                for (int mt = 0; mt < 2; mt++) {
                    const int row = wr * 32 + mt * 16 + lrow;
                    ldm4(a[mt], pa + (row * STRIDE + kb + lcol) * 2);
                }
#pragma unroll
                for (int ng = 0; ng < 4; ng++) {
                    const int row = wc * 64 + ng * 16 + lrow;
                    uint32_t bm[4];
                    ldm4(bm, pb + (row * STRIDE + kb + lcol) * 2);
                    mma16816(c[0][ng * 2],     a[0], bm[0], bm[2]);
                    mma16816(c[0][ng * 2 + 1], a[0], bm[1], bm[3]);
                    mma16816(c[1][ng * 2],     a[1], bm[0], bm[2]);
                    mma16816(c[1][ng * 2 + 1], a[1], bm[1], bm[3]);
                }
            }
        }
        __syncthreads();
    }

#pragma unroll
    for (int mt = 0; mt < 2; mt++) {
        const int r = m0 + wr * 32 + mt * 16 + gid;
#pragma unroll
        for (int nt = 0; nt < 8; nt++) {
            const int col = n0 + wc * 64 + nt * 8 + q * 2;
            *(float2*)(C + (long)r * ldc + col)       = make_float2(c[mt][nt][0], c[mt][nt][1]);
            *(float2*)(C + (long)(r + 8) * ldc + col) = make_float2(c[mt][nt][2], c[mt][nt][3]);
        }
    }
}

// ---------------------------------------------------------------------------
// Small fp32 GEMM: 64x64 tile (middle chain steps 3-5)
// ---------------------------------------------------------------------------
template <int TRANSA>
__global__ __launch_bounds__(256) void gemm64(
    const float* __restrict__ A, const float* __restrict__ B, float* __restrict__ C,
    int M, int N, int K,
    int lda, int ldb, int ldc,
    long sAb, long sAh, long sBb, long sBh, long sCb, long sCh,
    int nh, int nsplit, long splitStride)
{
    int z = blockIdx.z;
    int split = z % nsplit; z /= nsplit;
    int h = z % nh;
    int b = z / nh;
    A += (long)b * sAb + (long)h * sAh;
    B += (long)b * sBb + (long)h * sBh;
    C += (long)b * sCb + (long)h * sCh + (long)split * splitStride;

    const int Kc = K / nsplit;
    const int k0 = split * Kc;

    __shared__ float As[16][64];
    __shared__ float Bs[16][64];

    const int m0 = blockIdx.y * 64;
    const int n0 = blockIdx.x * 64;
    const int tid = threadIdx.x;
    const int tx = tid & 15;
    const int ty = tid >> 4;

    float acc[4][4];
#pragma unroll
    for (int i = 0; i < 4; i++)
#pragma unroll
        for (int j = 0; j < 4; j++) acc[i][j] = 0.f;

    for (int kt = 0; kt < Kc; kt += 16) {
        if (TRANSA) {
            int k  = tid >> 4;
            int m4 = (tid & 15) * 4;
            float4 v = *reinterpret_cast<const float4*>(
                &A[(long)(k0 + kt + k) * lda + m0 + m4]);
            *reinterpret_cast<float4*>(&As[k][m4]) = v;
        } else {
            int m  = tid >> 2;
            int k4 = (tid & 3) * 4;
            float4 v = *reinterpret_cast<const float4*>(
                &A[(long)(m0 + m) * lda + (k0 + kt + k4)]);
            As[k4 + 0][m] = v.x;
            As[k4 + 1][m] = v.y;
            As[k4 + 2][m] = v.z;
            As[k4 + 3][m] = v.w;
        }
        {
            int k  = tid >> 4;
            int n4 = (tid & 15) * 4;
            float4 v = *reinterpret_cast<const float4*>(
                &B[(long)(k0 + kt + k) * ldb + n0 + n4]);
            *reinterpret_cast<float4*>(&Bs[k][n4]) = v;
        }
        __syncthreads();

#pragma unroll
        for (int k = 0; k < 16; k++) {
            float4 a = *reinterpret_cast<const float4*>(&As[k][ty * 4]);
            float4 bb = *reinterpret_cast<const float4*>(&Bs[k][tx * 4]);
            float av[4] = {a.x, a.y, a.z, a.w};
            float bv[4] = {bb.x, bb.y, bb.z, bb.w};
#pragma unroll
            for (int i = 0; i < 4; i++)
#pragma unroll
                for (int j = 0; j < 4; j++)
                    acc[i][j] += av[i] * bv[j];
        }
        __syncthreads();
    }

#pragma unroll
    for (int i = 0; i < 4; i++) {
        int m = m0 + ty * 4 + i;
        float4 v = make_float4(acc[i][0], acc[i][1], acc[i][2], acc[i][3]);
        *reinterpret_cast<float4*>(&C[(long)m * ldc + n0 + tx * 4]) = v;
    }
}

template <int P>
__global__ void reduceP(float* __restrict__ dst, const float* __restrict__ src, int n)
{
    int i = blockIdx.x * 256 + threadIdx.x;
    if (i < n) {
        float s = 0.f;
#pragma unroll
        for (int p = 0; p < P; p++) s += src[(long)p * n + i];
        dst[i] = s;
    }
}

// ---------------------------------------------------------------------------
extern "C" void kernel_launch(void* const* d_in, const int* in_sizes, int n_in,
                              void* d_out, int out_size)
{
    const float* x  = (const float*)d_in[0];
    const float* Wq = (const float*)d_in[1];
    const float* Wk = (const float*)d_in[2];
    const float* Wv = (const float*)d_in[3];
    const float* Wo = (const float*)d_in[4];
    float* out = (float*)d_out;

    float *Gp1, *Gp2, *P, *Mp, *M2, *T2, *F;
    cudaGetSymbolAddress((void**)&Gp1, g_Gp1);
    cudaGetSymbolAddress((void**)&Gp2, g_Gp2);
    cudaGetSymbolAddress((void**)&P,   g_P);
    cudaGetSymbolAddress((void**)&Mp,  g_Mpart);
    cudaGetSymbolAddress((void**)&M2,  g_M2);
    cudaGetSymbolAddress((void**)&T2,  g_T2);
    cudaGetSymbolAddress((void**)&F,   g_F);

    __nv_bfloat16 *xh, *xl, *xTh, *xTl, *FTh, *FTl, *Gh, *Gl, *WkTh, *WkTl;
    cudaGetSymbolAddress((void**)&xh,   g_xh);
    cudaGetSymbolAddress((void**)&xl,   g_xl);
    cudaGetSymbolAddress((void**)&xTh,  g_xTh);
    cudaGetSymbolAddress((void**)&xTl,  g_xTl);
    cudaGetSymbolAddress((void**)&FTh,  g_FTh);
    cudaGetSymbolAddress((void**)&FTl,  g_FTl);
    cudaGetSymbolAddress((void**)&Gh,   g_Gh);
    cudaGetSymbolAddress((void**)&Gl,   g_Gl);
    cudaGetSymbolAddress((void**)&WkTh, g_WkTh);
    cudaGetSymbolAddress((void**)&WkTl, g_WkTl);

    const int TG1_SMEM = 2 * 2 * TILE_B;   // 40960
    const int TG3_SMEM = 2 * 4 * TILE_B;   // 81920
    cudaFuncSetAttribute(tgemm_bf16<3>, cudaFuncAttributeMaxDynamicSharedMemorySize, TG3_SMEM);
    cudaFuncSetAttribute(tgemm_bf16<1>, cudaFuncAttributeMaxDynamicSharedMemorySize, TG1_SMEM);

    const long LD   = (long)LL * DIN;
    const long GS   = (long)DIN * DIN;
    const long WKS  = (long)DIN * DK;
    const long PSH  = (long)DK * DIN;
    const long PSB  = (long)HH * PSH;
    const long MSH  = (long)DK * DV;
    const long MSB  = (long)HH * MSH;
    const long XTS  = (long)DIN * LL;

    // 0) split x; prep WkT
    split_x_kernel<<<dim3(DIN / 32, LL / 32, BB), dim3(32, 8)>>>(x, xh, xl, xTh, xTl);
    prep_WkT_kernel<<<dim3(DK / 32, DIN / 32, HH), dim3(32, 8)>>>(Wk, WkTh, WkTl);

    // 1) Gram, symmetric 2-product (split-K=8 -> grid 256, 2 CTAs/SM @40KB)
    tgemm_bf16<1><<<dim3(4, 4, BB * 8), 256, TG1_SMEM>>>(
        xTh, xTh, xTh, xTh, Gp1,
        LL, LL, LL, DIN, XTS, XTS, GS, 8, (long)BB * GS);
    tgemm_bf16<1><<<dim3(4, 4, BB * 8), 256, TG1_SMEM>>>(
        xTh, xTh, xTl, xTl, Gp2,
        LL, LL, LL, DIN, XTS, XTS, GS, 8, (long)BB * GS);
    reduceG_kernel<<<dim3(16, 16, BB), dim3(32, 8)>>>(Gp1, Gp2, Gh, Gl);

    // 2) P_all[b] = WkT_flat @ G[b]  (split-K=4 -> grid 128; partials reuse Gp1)
    tgemm_bf16<3><<<dim3(4, 4, BB * 4), 256, TG3_SMEM>>>(
        WkTh, WkTl, Gh, Gl, Gp1,
        DIN, DIN, DIN, DIN, 0, GS, GS, 4, (long)BB * GS);
    reduceP<4><<<(int)((BB * GS + 255) / 256), 256>>>(P, Gp1, BB * GS);

    // 3) M[b,h] = P[b,h] @ Wv[h]  (64x64, K=512), split-K=8 -> 128 CTAs
    gemm64<0><<<dim3(1, 1, BB * HH * 8), 256>>>(
        P, Wv, Mp, DK, DV, DIN,
        DIN, DV, DV,
        PSB, PSH, 0, WKS, MSB, MSH,
        HH, 8, (long)BB * HH * DK * DV);
    reduceP<8><<<(BB * HH * DK * DV + 255) / 256, 256>>>(M2, Mp, BB * HH * DK * DV);

    // 4) T2cat[b][:, h*64:] = Wq[h] @ M[b,h]  (512x64, K=64), 128 CTAs
    gemm64<0><<<dim3(1, 8, BB * HH), 256>>>(
        Wq, M2, T2, DIN, DV, DK,
        DK, DV, HH * DV,
        0, WKS, MSB, MSH, (long)DIN * HH * DV, (long)DV,
        HH, 1, 0);

    // 5) F[b] = T2cat[b] @ Wo_flat  (split-K=4 -> 256 CTAs; partials reuse Gp2)
    gemm64<0><<<dim3(8, 8, BB * 4), 256>>>(
        T2, Wo, Gp2, DIN, DOUT, HH * DV,
        HH * DV, DOUT, DOUT,
        (long)DIN * HH * DV, 0, 0, 0, (long)DIN * DOUT, 0,
        1, 4, (long)BB * DIN * DOUT);
    reduceP<4><<<(int)((BB * (long)DIN * DOUT + 255) / 256), 256>>>(F, Gp2, BB * DIN * DOUT);

    // 5b) split F^T
    split_FT_kernel<<<dim3(DOUT / 32, DIN / 32, BB), dim3(32, 8)>>>(F, FTh, FTl);

    // 6) out[b] = x[b] @ F[b]  (tensor, 3-product), 256 CTAs
    tgemm_bf16<3><<<dim3(4, 32, BB), 256, TG3_SMEM>>>(
        xh, xl, FTh, FTl, out,
        DIN, DIN, DIN, DOUT,
        LD, (long)DOUT * DIN, (long)LL * DOUT, 1, 0);
}

// round 11
// speedup vs baseline: 2.2263x; 1.0421x over previous
#include <cuda_runtime.h>
#include <cuda_bf16.h>
#include <cstdint>

#define BB 2
#define LL 4096
#define DIN 512
#define HH 8
#define DK 64
#define DV 64
#define DOUT 512

// ---------------------------------------------------------------------------
// Scratch (__device__ globals; no allocations allowed)
// ---------------------------------------------------------------------------
__device__ float g_Gp1[8 * BB * DIN * DIN];       // Gram partials XhXh / step2 partials
__device__ float g_Gp2[8 * BB * DIN * DIN];       // Gram partials XhXl / step5 partials
__device__ float g_P [BB * HH * DK * DIN];        // P_all[b] (512x512)
__device__ float g_Mpart[8 * BB * HH * DK * DV];  // step-3 split-K partials
__device__ float g_M2[BB * HH * DK * DV];         // M[b,h] = P Wv
__device__ float g_T2[BB * DIN * (HH * DV)];      // T2cat[b] (512 x 512)
__device__ float g_F [BB * DIN * DOUT];           // F[b] (512 x 512)

// bf16 hi/lo split arrays
__device__ __nv_bfloat16 g_xh [BB * LL * DIN];    // x direct  [b][l][d]
__device__ __nv_bfloat16 g_xl [BB * LL * DIN];
__device__ __nv_bfloat16 g_xTh[BB * DIN * LL];    // x^T       [b][d][l]
__device__ __nv_bfloat16 g_xTl[BB * DIN * LL];
__device__ __nv_bfloat16 g_FTh[BB * DOUT * DIN];  // F^T       [b][o][d]
__device__ __nv_bfloat16 g_FTl[BB * DOUT * DIN];
__device__ __nv_bfloat16 g_Gh [BB * DIN * DIN];   // G bf16 hi (symmetric)
__device__ __nv_bfloat16 g_Gl [BB * DIN * DIN];   // G bf16 lo
__device__ __nv_bfloat16 g_WkTh[HH * DK * DIN];   // WkT flat: row h*64+k, col d
__device__ __nv_bfloat16 g_WkTl[HH * DK * DIN];

// ---------------------------------------------------------------------------
// Helpers
// ---------------------------------------------------------------------------
__device__ __forceinline__ uint32_t smem_u32(const void* p) {
    uint32_t a;
    asm("{ .reg .u64 t; cvta.to.shared.u64 t, %1; cvt.u32.u64 %0, t; }" : "=r"(a) : "l"(p));
    return a;
}
__device__ __forceinline__ void cp_async16(uint32_t saddr, const void* gptr) {
    asm volatile("cp.async.ca.shared.global [%0], [%1], 16;" :: "r"(saddr), "l"(gptr));
}
__device__ __forceinline__ void ldm4(uint32_t* r, uint32_t addr) {
    asm volatile("ldmatrix.sync.aligned.m8n8.x4.shared.b16 {%0,%1,%2,%3}, [%4];"
        : "=r"(r[0]), "=r"(r[1]), "=r"(r[2]), "=r"(r[3]) : "r"(addr));
}
__device__ __forceinline__ void mma16816(float* c, const uint32_t* a,
                                         uint32_t b0, uint32_t b1) {
    asm volatile(
        "mma.sync.aligned.m16n8k16.row.col.f32.bf16.bf16.f32 "
        "{%0,%1,%2,%3}, {%4,%5,%6,%7}, {%8,%9}, {%0,%1,%2,%3};"
        : "+f"(c[0]), "+f"(c[1]), "+f"(c[2]), "+f"(c[3])
        : "r"(a[0]), "r"(a[1]), "r"(a[2]), "r"(a[3]), "r"(b0), "r"(b1));
}
__device__ __forceinline__ void bf16split(float v, __nv_bfloat16& h, __nv_bfloat16& l) {
    h = __float2bfloat16(v);
    l = __float2bfloat16(v - __bfloat162float(h));
}

// ---------------------------------------------------------------------------
// Split / prep kernels
// ---------------------------------------------------------------------------
__global__ __launch_bounds__(256) void split_x_kernel(
    const float* __restrict__ x,
    __nv_bfloat16* __restrict__ xh, __nv_bfloat16* __restrict__ xl,
    __nv_bfloat16* __restrict__ xTh, __nv_bfloat16* __restrict__ xTl)
{
    __shared__ float tile[32][33];
    const int tx = threadIdx.x, ty = threadIdx.y;
    const int b = blockIdx.z, d0 = blockIdx.x * 32, l0 = blockIdx.y * 32;
    const float* xb = x + (long)b * LL * DIN;

#pragma unroll
    for (int i = ty; i < 32; i += 8) {
        float v = xb[(long)(l0 + i) * DIN + d0 + tx];
        tile[i][tx] = v;
        __nv_bfloat16 h, lo; bf16split(v, h, lo);
        long o = (long)b * LL * DIN + (long)(l0 + i) * DIN + d0 + tx;
        xh[o] = h; xl[o] = lo;
    }
    __syncthreads();
#pragma unroll
    for (int i = ty; i < 32; i += 8) {
        float v = tile[tx][i];
        __nv_bfloat16 h, lo; bf16split(v, h, lo);
        long o = (long)b * DIN * LL + (long)(d0 + i) * LL + l0 + tx;
        xTh[o] = h; xTl[o] = lo;
    }
}

__global__ __launch_bounds__(256) void split_FT_kernel(
    const float* __restrict__ F,
    __nv_bfloat16* __restrict__ FTh, __nv_bfloat16* __restrict__ FTl)
{
    __shared__ float tile[32][33];
    const int tx = threadIdx.x, ty = threadIdx.y;
    const int b = blockIdx.z, o0 = blockIdx.x * 32, d0 = blockIdx.y * 32;
    const float* Fb = F + (long)b * DIN * DOUT;

#pragma unroll
    for (int i = ty; i < 32; i += 8)
        tile[i][tx] = Fb[(long)(d0 + i) * DOUT + o0 + tx];
    __syncthreads();
#pragma unroll
    for (int i = ty; i < 32; i += 8) {
        float v = tile[tx][i];
        __nv_bfloat16 h, lo; bf16split(v, h, lo);
        long o = (long)b * DOUT * DIN + (long)(o0 + i) * DIN + d0 + tx;
        FTh[o] = h; FTl[o] = lo;
    }
}

// WkT[h*64+k][d] = Wk[h][d][k], bf16 hi/lo
__global__ __launch_bounds__(256) void prep_WkT_kernel(
    const float* __restrict__ Wk,
    __nv_bfloat16* __restrict__ WkTh, __nv_bfloat16* __restrict__ WkTl)
{
    __shared__ float tile[32][33];
    const int tx = threadIdx.x, ty = threadIdx.y;
    const int h = blockIdx.z, k0 = blockIdx.x * 32, d0 = blockIdx.y * 32;
    const float* W = Wk + (long)h * DIN * DK;

#pragma unroll
    for (int r = ty; r < 32; r += 8)
        tile[r][tx] = W[(long)(d0 + r) * DK + k0 + tx];
    __syncthreads();
#pragma unroll
    for (int ii = ty; ii < 32; ii += 8) {
        float v = tile[tx][ii];
        __nv_bfloat16 hh, lo; bf16split(v, hh, lo);
        long o = (long)(h * DK + k0 + ii) * DIN + d0 + tx;
        WkTh[o] = hh; WkTl[o] = lo;
    }
}

// G = sum_p Gp1 + sum_p Gp2 + (sum_p Gp2)^T ; emit bf16 hi/lo  (P=8 partials)
__global__ __launch_bounds__(256) void reduceG_kernel(
    const float* __restrict__ Gp1, const float* __restrict__ Gp2,
    __nv_bfloat16* __restrict__ Gh, __nv_bfloat16* __restrict__ Gl)
{
    __shared__ float T[32][33];
    const int tx = threadIdx.x, ty = threadIdx.y;
    const int b = blockIdx.z, j0 = blockIdx.x * 32, i0 = blockIdx.y * 32;
    const long GSL = (long)DIN * DIN;
    const long PS = (long)BB * GSL;

#pragma unroll
    for (int r = ty; r < 32; r += 8) {
        float s = 0.f;
#pragma unroll
        for (int p = 0; p < 8; p++)
            s += Gp2[p * PS + b * GSL + (long)(j0 + r) * DIN + i0 + tx];
        T[r][tx] = s;
    }
    __syncthreads();
#pragma unroll
    for (int ii = ty; ii < 32; ii += 8) {
        const long ro = (long)(i0 + ii) * DIN + j0 + tx;
        float s = 0.f;
#pragma unroll
        for (int p = 0; p < 8; p++)
            s += Gp1[p * PS + b * GSL + ro] + Gp2[p * PS + b * GSL + ro];
        s += T[tx][ii];
        __nv_bfloat16 h, lo; bf16split(s, h, lo);
        Gh[b * GSL + ro] = h; Gl[b * GSL + ro] = lo;
    }
}

// ---------------------------------------------------------------------------
// bf16 tensor GEMM: C[128x128 fp32] = sum_k A[m,k]*B[n,k]
// PR=3: AhBh + AhBl + AlBh (4 smem tiles/buffer).
// PR=1: AhBh only (2 smem tiles/buffer).
// KTv: k-chunk (32 or 64). GRAM=1: grid.z doubled; top half uses B=Bl_in,
//      C=C2 (merged two-product launch for the symmetric Gram scheme).
// ---------------------------------------------------------------------------
template <int PR, int KTv, int GRAM>
__global__ __launch_bounds__(256, 2) void tgemm_bf16(
    const __nv_bfloat16* __restrict__ Ah, const __nv_bfloat16* __restrict__ Al,
    const __nv_bfloat16* __restrict__ Bh, const __nv_bfloat16* __restrict__ Bl,
    float* __restrict__ C, float* __restrict__ C2,
    int K, int lda, int ldb, int ldc,
    long sAb, long sBb, long sCb, int nsplit, long splitStride)
{
    constexpr int STRIDEv = KTv + 8;
    constexpr int TILE = 128 * STRIDEv * 2;
    constexpr int NTILE = (PR == 1) ? 2 : 4;
    constexpr int BUF_Bv = NTILE * TILE;
    constexpr int S_AH = 0;
    constexpr int S_AL = (PR == 1) ? 0 : TILE;
    constexpr int S_BH = (PR == 1) ? TILE : 2 * TILE;
    constexpr int S_BL = (PR == 1) ? TILE : 3 * TILE;
    constexpr int SEGS = KTv / 8;      // uint4 segments per row

    extern __shared__ char sm[];
    const uint32_t sb = smem_u32(sm);

    const int tid = threadIdx.x;
    const int w = tid >> 5;
    const int lane = tid & 31;
    const int gid = lane >> 2;
    const int q = lane & 3;
    const int wr = w & 3;
    const int wc = w >> 2;

    int z = blockIdx.z;
    if (GRAM) {
        const int per = gridDim.z >> 1;
        if (z >= per) { z -= per; Bh = Bl; C = C2; }
    }
    const int split = z % nsplit;
    const int b = z / nsplit;
    Ah += (long)b * sAb; Al += (long)b * sAb;
    Bh += (long)b * sBb; Bl += (long)b * sBb;
    C += (long)b * sCb + (long)split * splitStride;

    const int m0 = blockIdx.y * 128;
    const int n0 = blockIdx.x * 128;
    const int Kc = K / nsplit;
    const int k0 = split * Kc;
    const int nchunks = Kc / KTv;

    float c[2][8][4];
#pragma unroll
    for (int mt = 0; mt < 2; mt++)
#pragma unroll
        for (int nt = 0; nt < 8; nt++)
#pragma unroll
            for (int i = 0; i < 4; i++) c[mt][nt][i] = 0.f;

    auto issue = [&](int ch, int buf) {
        const int kc = k0 + ch * KTv;
        const uint32_t base = sb + buf * BUF_Bv;
#pragma unroll
        for (int t = 0; t < 4; t++) {
            if (PR == 1 && (t & 1)) continue;   // skip lo tiles
            const __nv_bfloat16* gp = (t == 0) ? Ah : (t == 1) ? Al : (t == 2) ? Bh : Bl;
            const int off = (t == 0) ? S_AH : (t == 1) ? S_AL : (t == 2) ? S_BH : S_BL;
            const int ld = (t < 2) ? lda : ldb;
            const int rb = (t < 2) ? m0 : n0;
#pragma unroll
            for (int p = 0; p < KTv / 16; p++) {
                const int f = p * 256 + tid;
                const int row = f / SEGS;
                const int seg = f % SEGS;
                cp_async16(base + off + (row * STRIDEv + seg * 8) * 2,
                           gp + (long)(rb + row) * ld + kc + seg * 8);
            }
        }
        asm volatile("cp.async.commit_group;" ::: "memory");
    };

    issue(0, 0);

    const int lrow = (lane & 7) + ((lane >> 3) & 1) * 8;
    const int lcol = (lane >> 4) * 8;

    for (int ch = 0; ch < nchunks; ch++) {
        const int cur = ch & 1;
        if (ch + 1 < nchunks) {
            issue(ch + 1, cur ^ 1);
            asm volatile("cp.async.wait_group 1;" ::: "memory");
        } else {
            asm volatile("cp.async.wait_group 0;" ::: "memory");
        }
        __syncthreads();

        const uint32_t base = sb + cur * BUF_Bv;
#pragma unroll
        for (int ks = 0; ks < KTv / 16; ks++) {
            const int kb = ks * 16;
#pragma unroll
            for (int pr = 0; pr < PR; pr++) {
                const uint32_t pa = base + ((pr == 2) ? S_AL : S_AH);
                const uint32_t pb = base + ((pr == 1) ? S_BL : S_BH);

                uint32_t a[2][4];
#pragma unroll
                for (int mt = 0; mt < 2; mt++) {
                    const int row = wr * 32 + mt * 16 + lrow;
                    ldm4(a[mt], pa + (row * STRIDEv + kb + lcol) * 2);
                }
#pragma unroll
                for (int ng = 0; ng < 4; ng++) {
                    const int row = wc * 64 + ng * 16 + lrow;
                    uint32_t bm[4];
                    ldm4(bm, pb + (row * STRIDEv + kb + lcol) * 2);
                    mma16816(c[0][ng * 2],     a[0], bm[0], bm[2]);
                    mma16816(c[0][ng * 2 + 1], a[0], bm[1], bm[3]);
                    mma16816(c[1][ng * 2],     a[1], bm[0], bm[2]);
                    mma16816(c[1][ng * 2 + 1], a[1], bm[1], bm[3]);
                }
            }
        }
        __syncthreads();
    }

#pragma unroll
    for (int mt = 0; mt < 2; mt++) {
        const int r = m0 + wr * 32 + mt * 16 + gid;
#pragma unroll
        for (int nt = 0; nt < 8; nt++) {
            const int col = n0 + wc * 64 + nt * 8 + q * 2;
            *(float2*)(C + (long)r * ldc + col)       = make_float2(c[mt][nt][0], c[mt][nt][1]);
            *(float2*)(C + (long)(r + 8) * ldc + col) = make_float2(c[mt][nt][2], c[mt][nt][3]);
        }
    }
}

// ---------------------------------------------------------------------------
// Small fp32 GEMM: 64x64 tile (middle chain steps 3-5)
// ---------------------------------------------------------------------------
template <int TRANSA>
__global__ __launch_bounds__(256) void gemm64(
    const float* __restrict__ A, const float* __restrict__ B, float* __restrict__ C,
    int M, int N, int K,
    int lda, int ldb, int ldc,
    long sAb, long sAh, long sBb, long sBh, long sCb, long sCh,
    int nh, int nsplit, long splitStride)
{
    int z = blockIdx.z;
    int split = z % nsplit; z /= nsplit;
    int h = z % nh;
    int b = z / nh;
    A += (long)b * sAb + (long)h * sAh;
    B += (long)b * sBb + (long)h * sBh;
    C += (long)b * sCb + (long)h * sCh + (long)split * splitStride;

    const int Kc = K / nsplit;
    const int k0 = split * Kc;

    __shared__ float As[16][64];
    __shared__ float Bs[16][64];

    const int m0 = blockIdx.y * 64;
    const int n0 = blockIdx.x * 64;
    const int tid = threadIdx.x;
    const int tx = tid & 15;
    const int ty = tid >> 4;

    float acc[4][4];
#pragma unroll
    for (int i = 0; i < 4; i++)
#pragma unroll
        for (int j = 0; j < 4; j++) acc[i][j] = 0.f;

    for (int kt = 0; kt < Kc; kt += 16) {
        if (TRANSA) {
            int k  = tid >> 4;
            int m4 = (tid & 15) * 4;
            float4 v = *reinterpret_cast<const float4*>(
                &A[(long)(k0 + kt + k) * lda + m0 + m4]);
            *reinterpret_cast<float4*>(&As[k][m4]) = v;
        } else {
            int m  = tid >> 2;
            int k4 = (tid & 3) * 4;
            float4 v = *reinterpret_cast<const float4*>(
                &A[(long)(m0 + m) * lda + (k0 + kt + k4)]);
            As[k4 + 0][m] = v.x;
            As[k4 + 1][m] = v.y;
            As[k4 + 2][m] = v.z;
            As[k4 + 3][m] = v.w;
        }
        {
            int k  = tid >> 4;
            int n4 = (tid & 15) * 4;
            float4 v = *reinterpret_cast<const float4*>(
                &B[(long)(k0 + kt + k) * ldb + n0 + n4]);
            *reinterpret_cast<float4*>(&Bs[k][n4]) = v;
        }
        __syncthreads();

#pragma unroll
        for (int k = 0; k < 16; k++) {
            float4 a = *reinterpret_cast<const float4*>(&As[k][ty * 4]);
            float4 bb = *reinterpret_cast<const float4*>(&Bs[k][tx * 4]);
            float av[4] = {a.x, a.y, a.z, a.w};
            float bv[4] = {bb.x, bb.y, bb.z, bb.w};
#pragma unroll
            for (int i = 0; i < 4; i++)
#pragma unroll
                for (int j = 0; j < 4; j++)
                    acc[i][j] += av[i] * bv[j];
        }
        __syncthreads();
    }

#pragma unroll
    for (int i = 0; i < 4; i++) {
        int m = m0 + ty * 4 + i;
        float4 v = make_float4(acc[i][0], acc[i][1], acc[i][2], acc[i][3]);
        *reinterpret_cast<float4*>(&C[(long)m * ldc + n0 + tx * 4]) = v;
    }
}

template <int P>
__global__ void reduceP(float* __restrict__ dst, const float* __restrict__ src, int n)
{
    int i = blockIdx.x * 256 + threadIdx.x;
    if (i < n) {
        float s = 0.f;
#pragma unroll
        for (int p = 0; p < P; p++) s += src[(long)p * n + i];
        dst[i] = s;
    }
}

// ---------------------------------------------------------------------------
extern "C" void kernel_launch(void* const* d_in, const int* in_sizes, int n_in,
                              void* d_out, int out_size)
{
    const float* x  = (const float*)d_in[0];
    const float* Wq = (const float*)d_in[1];
    const float* Wk = (const float*)d_in[2];
    const float* Wv = (const float*)d_in[3];
    const float* Wo = (const float*)d_in[4];
    float* out = (float*)d_out;

    float *Gp1, *Gp2, *P, *Mp, *M2, *T2, *F;
    cudaGetSymbolAddress((void**)&Gp1, g_Gp1);
    cudaGetSymbolAddress((void**)&Gp2, g_Gp2);
    cudaGetSymbolAddress((void**)&P,   g_P);
    cudaGetSymbolAddress((void**)&Mp,  g_Mpart);
    cudaGetSymbolAddress((void**)&M2,  g_M2);
    cudaGetSymbolAddress((void**)&T2,  g_T2);
    cudaGetSymbolAddress((void**)&F,   g_F);

    __nv_bfloat16 *xh, *xl, *xTh, *xTl, *FTh, *FTl, *Gh, *Gl, *WkTh, *WkTl;
    cudaGetSymbolAddress((void**)&xh,   g_xh);
    cudaGetSymbolAddress((void**)&xl,   g_xl);
    cudaGetSymbolAddress((void**)&xTh,  g_xTh);
    cudaGetSymbolAddress((void**)&xTl,  g_xTl);
    cudaGetSymbolAddress((void**)&FTh,  g_FTh);
    cudaGetSymbolAddress((void**)&FTl,  g_FTl);
    cudaGetSymbolAddress((void**)&Gh,   g_Gh);
    cudaGetSymbolAddress((void**)&Gl,   g_Gl);
    cudaGetSymbolAddress((void**)&WkTh, g_WkTh);
    cudaGetSymbolAddress((void**)&WkTl, g_WkTl);

    const int TG1_SMEM = 2 * 2 * (128 * 72 * 2);   // KT=64, PR=1: 73728
    const int TG3_SMEM = 2 * 4 * (128 * 40 * 2);   // KT=32, PR=3: 81920
    cudaFuncSetAttribute((const void*)tgemm_bf16<1, 64, 1>,
                         cudaFuncAttributeMaxDynamicSharedMemorySize, TG1_SMEM);
    cudaFuncSetAttribute((const void*)tgemm_bf16<3, 32, 0>,
                         cudaFuncAttributeMaxDynamicSharedMemorySize, TG3_SMEM);

    const long LD   = (long)LL * DIN;
    const long GS   = (long)DIN * DIN;
    const long WKS  = (long)DIN * DK;
    const long PSH  = (long)DK * DIN;
    const long PSB  = (long)HH * PSH;
    const long MSH  = (long)DK * DV;
    const long MSB  = (long)HH * MSH;
    const long XTS  = (long)DIN * LL;

    // 0) split x; prep WkT
    split_x_kernel<<<dim3(DIN / 32, LL / 32, BB), dim3(32, 8)>>>(x, xh, xl, xTh, xTl);
    prep_WkT_kernel<<<dim3(DK / 32, DIN / 32, HH), dim3(32, 8)>>>(Wk, WkTh, WkTl);

    // 1) Gram, both symmetric products in ONE launch (KT=64, split-K=8):
    //    z < 16: Gp1 = Xh^T Xh ; z >= 16: Gp2 = Xh^T Xl.  grid 512 -> good balance.
    tgemm_bf16<1, 64, 1><<<dim3(4, 4, BB * 8 * 2), 256, TG1_SMEM>>>(
        xTh, xTh, xTh, xTl, Gp1, Gp2,
        LL, LL, LL, DIN, XTS, XTS, GS, 8, (long)BB * GS);
    reduceG_kernel<<<dim3(16, 16, BB), dim3(32, 8)>>>(Gp1, Gp2, Gh, Gl);

    // 2) P_all[b] = WkT_flat @ G[b]  (split-K=4 -> grid 128; partials reuse Gp1)
    tgemm_bf16<3, 32, 0><<<dim3(4, 4, BB * 4), 256, TG3_SMEM>>>(
        WkTh, WkTl, Gh, Gl, Gp1, Gp1,
        DIN, DIN, DIN, DIN, 0, GS, GS, 4, (long)BB * GS);
    reduceP<4><<<(int)((BB * GS + 255) / 256), 256>>>(P, Gp1, BB * GS);

    // 3) M[b,h] = P[b,h] @ Wv[h]  (64x64, K=512), split-K=8 -> 128 CTAs
    gemm64<0><<<dim3(1, 1, BB * HH * 8), 256>>>(
        P, Wv, Mp, DK, DV, DIN,
        DIN, DV, DV,
        PSB, PSH, 0, WKS, MSB, MSH,
        HH, 8, (long)BB * HH * DK * DV);
    reduceP<8><<<(BB * HH * DK * DV + 255) / 256, 256>>>(M2, Mp, BB * HH * DK * DV);

    // 4) T2cat[b][:, h*64:] = Wq[h] @ M[b,h]  (512x64, K=64), 128 CTAs
    gemm64<0><<<dim3(1, 8, BB * HH), 256>>>(
        Wq, M2, T2, DIN, DV, DK,
        DK, DV, HH * DV,
        0, WKS, MSB, MSH, (long)DIN * HH * DV, (long)DV,
        HH, 1, 0);

    // 5) F[b] = T2cat[b] @ Wo_flat  (split-K=4 -> 256 CTAs; partials reuse Gp2)
    gemm64<0><<<dim3(8, 8, BB * 4), 256>>>(
        T2, Wo, Gp2, DIN, DOUT, HH * DV,
        HH * DV, DOUT, DOUT,
        (long)DIN * HH * DV, 0, 0, 0, (long)DIN * DOUT, 0,
        1, 4, (long)BB * DIN * DOUT);
    reduceP<4><<<(int)((BB * (long)DIN * DOUT + 255) / 256), 256>>>(F, Gp2, BB * DIN * DOUT);

    // 5b) split F^T
    split_FT_kernel<<<dim3(DOUT / 32, DIN / 32, BB), dim3(32, 8)>>>(F, FTh, FTl);

    // 6) out[b] = x[b] @ F[b]  (tensor, 3-product), 256 CTAs
    tgemm_bf16<3, 32, 0><<<dim3(4, 32, BB), 256, TG3_SMEM>>>(
        xh, xl, FTh, FTl, out, out,
        DIN, DIN, DIN, DOUT,
        LD, (long)DOUT * DIN, (long)LL * DOUT, 1, 0);
}

// round 12
// speedup vs baseline: 2.3462x; 1.0539x over previous
#include <cuda_runtime.h>
#include <cuda_bf16.h>
#include <cstdint>

#define BB 2
#define LL 4096
#define DIN 512
#define HH 8
#define DK 64
#define DV 64
#define DOUT 512

// ---------------------------------------------------------------------------
// Scratch (__device__ globals; no allocations allowed)
// ---------------------------------------------------------------------------
__device__ float g_Gp1[4 * BB * DIN * DIN];       // Gram partials XhXh / step2 partials
__device__ float g_Gp2[4 * BB * DIN * DIN];       // Gram partials XhXl / step5 partials
__device__ float g_P [BB * HH * DK * DIN];        // P_all[b] (512x512)
__device__ float g_Mpart[8 * BB * HH * DK * DV];  // step-3 split-K partials
__device__ float g_M2[BB * HH * DK * DV];         // M[b,h] = P Wv
__device__ float g_T2[BB * DIN * (HH * DV)];      // T2cat[b] (512 x 512)

// bf16 hi/lo split arrays
__device__ __nv_bfloat16 g_xh [BB * LL * DIN];    // x direct  [b][l][d]
__device__ __nv_bfloat16 g_xl [BB * LL * DIN];
__device__ __nv_bfloat16 g_xTh[BB * DIN * LL];    // x^T       [b][d][l]
__device__ __nv_bfloat16 g_xTl[BB * DIN * LL];
__device__ __nv_bfloat16 g_FTh[BB * DOUT * DIN];  // F^T       [b][o][d]
__device__ __nv_bfloat16 g_FTl[BB * DOUT * DIN];
__device__ __nv_bfloat16 g_Gh [BB * DIN * DIN];   // G bf16 hi (symmetric)
__device__ __nv_bfloat16 g_Gl [BB * DIN * DIN];   // G bf16 lo
__device__ __nv_bfloat16 g_WkTh[HH * DK * DIN];   // WkT flat: row h*64+k, col d
__device__ __nv_bfloat16 g_WkTl[HH * DK * DIN];

// ---------------------------------------------------------------------------
// Helpers
// ---------------------------------------------------------------------------
__device__ __forceinline__ uint32_t smem_u32(const void* p) {
    uint32_t a;
    asm("{ .reg .u64 t; cvta.to.shared.u64 t, %1; cvt.u32.u64 %0, t; }" : "=r"(a) : "l"(p));
    return a;
}
__device__ __forceinline__ void cp_async16(uint32_t saddr, const void* gptr) {
    asm volatile("cp.async.ca.shared.global [%0], [%1], 16;" :: "r"(saddr), "l"(gptr));
}
__device__ __forceinline__ void ldm4(uint32_t* r, uint32_t addr) {
    asm volatile("ldmatrix.sync.aligned.m8n8.x4.shared.b16 {%0,%1,%2,%3}, [%4];"
        : "=r"(r[0]), "=r"(r[1]), "=r"(r[2]), "=r"(r[3]) : "r"(addr));
}
__device__ __forceinline__ void mma16816(float* c, const uint32_t* a,
                                         uint32_t b0, uint32_t b1) {
    asm volatile(
        "mma.sync.aligned.m16n8k16.row.col.f32.bf16.bf16.f32 "
        "{%0,%1,%2,%3}, {%4,%5,%6,%7}, {%8,%9}, {%0,%1,%2,%3};"
        : "+f"(c[0]), "+f"(c[1]), "+f"(c[2]), "+f"(c[3])
        : "r"(a[0]), "r"(a[1]), "r"(a[2]), "r"(a[3]), "r"(b0), "r"(b1));
}
__device__ __forceinline__ void bf16split(float v, __nv_bfloat16& h, __nv_bfloat16& l) {
    h = __float2bfloat16(v);
    l = __float2bfloat16(v - __bfloat162float(h));
}

// ---------------------------------------------------------------------------
// Split / prep kernels
// ---------------------------------------------------------------------------
__global__ __launch_bounds__(256) void split_x_kernel(
    const float* __restrict__ x,
    __nv_bfloat16* __restrict__ xh, __nv_bfloat16* __restrict__ xl,
    __nv_bfloat16* __restrict__ xTh, __nv_bfloat16* __restrict__ xTl)
{
    __shared__ float tile[32][33];
    const int tx = threadIdx.x, ty = threadIdx.y;
    const int b = blockIdx.z, d0 = blockIdx.x * 32, l0 = blockIdx.y * 32;
    const float* xb = x + (long)b * LL * DIN;

#pragma unroll
    for (int i = ty; i < 32; i += 8) {
        float v = xb[(long)(l0 + i) * DIN + d0 + tx];
        tile[i][tx] = v;
        __nv_bfloat16 h, lo; bf16split(v, h, lo);
        long o = (long)b * LL * DIN + (long)(l0 + i) * DIN + d0 + tx;
        xh[o] = h; xl[o] = lo;
    }
    __syncthreads();
#pragma unroll
    for (int i = ty; i < 32; i += 8) {
        float v = tile[tx][i];
        __nv_bfloat16 h, lo; bf16split(v, h, lo);
        long o = (long)b * DIN * LL + (long)(d0 + i) * LL + l0 + tx;
        xTh[o] = h; xTl[o] = lo;
    }
}

// WkT[h*64+k][d] = Wk[h][d][k], bf16 hi/lo
__global__ __launch_bounds__(256) void prep_WkT_kernel(
    const float* __restrict__ Wk,
    __nv_bfloat16* __restrict__ WkTh, __nv_bfloat16* __restrict__ WkTl)
{
    __shared__ float tile[32][33];
    const int tx = threadIdx.x, ty = threadIdx.y;
    const int h = blockIdx.z, k0 = blockIdx.x * 32, d0 = blockIdx.y * 32;
    const float* W = Wk + (long)h * DIN * DK;

#pragma unroll
    for (int r = ty; r < 32; r += 8)
        tile[r][tx] = W[(long)(d0 + r) * DK + k0 + tx];
    __syncthreads();
#pragma unroll
    for (int ii = ty; ii < 32; ii += 8) {
        float v = tile[tx][ii];
        __nv_bfloat16 hh, lo; bf16split(v, hh, lo);
        long o = (long)(h * DK + k0 + ii) * DIN + d0 + tx;
        WkTh[o] = hh; WkTl[o] = lo;
    }
}

// G = sum_p Gp1 + sum_p Gp2 + (sum_p Gp2)^T ; emit bf16 hi/lo  (4 partials)
__global__ __launch_bounds__(256) void reduceG_kernel(
    const float* __restrict__ Gp1, const float* __restrict__ Gp2,
    __nv_bfloat16* __restrict__ Gh, __nv_bfloat16* __restrict__ Gl)
{
    __shared__ float T[32][33];
    const int tx = threadIdx.x, ty = threadIdx.y;
    const int b = blockIdx.z, j0 = blockIdx.x * 32, i0 = blockIdx.y * 32;
    const long GSL = (long)DIN * DIN;
    const long PS = (long)BB * GSL;

#pragma unroll
    for (int r = ty; r < 32; r += 8) {
        float s = 0.f;
#pragma unroll
        for (int p = 0; p < 4; p++)
            s += Gp2[p * PS + b * GSL + (long)(j0 + r) * DIN + i0 + tx];
        T[r][tx] = s;
    }
    __syncthreads();
#pragma unroll
    for (int ii = ty; ii < 32; ii += 8) {
        const long ro = (long)(i0 + ii) * DIN + j0 + tx;
        float s = 0.f;
#pragma unroll
        for (int p = 0; p < 4; p++)
            s += Gp1[p * PS + b * GSL + ro] + Gp2[p * PS + b * GSL + ro];
        s += T[tx][ii];
        __nv_bfloat16 h, lo; bf16split(s, h, lo);
        Gh[b * GSL + ro] = h; Gl[b * GSL + ro] = lo;
    }
}

// FT[b][o][d] = split( sum_p Fp[p][b][d][o] )  — fused reduce + transpose + split
__global__ __launch_bounds__(256) void reduceF_splitFT_kernel(
    const float* __restrict__ Fp,
    __nv_bfloat16* __restrict__ FTh, __nv_bfloat16* __restrict__ FTl)
{
    __shared__ float tile[32][33];
    const int tx = threadIdx.x, ty = threadIdx.y;
    const int b = blockIdx.z, o0 = blockIdx.x * 32, d0 = blockIdx.y * 32;
    const long FS = (long)DIN * DOUT;
    const long PS = (long)BB * FS;

#pragma unroll
    for (int i = ty; i < 32; i += 8) {
        float s = 0.f;
#pragma unroll
        for (int p = 0; p < 4; p++)
            s += Fp[p * PS + b * FS + (long)(d0 + i) * DOUT + o0 + tx];
        tile[i][tx] = s;
    }
    __syncthreads();
#pragma unroll
    for (int i = ty; i < 32; i += 8) {
        float v = tile[tx][i];      // element (d = d0+tx, o = o0+i)
        __nv_bfloat16 h, lo; bf16split(v, h, lo);
        long o = (long)b * DOUT * DIN + (long)(o0 + i) * DIN + d0 + tx;
        FTh[o] = h; FTl[o] = lo;
    }
}

// ---------------------------------------------------------------------------
// bf16 tensor GEMM: C[128x128 fp32] = sum_k A[m,k]*B[n,k]
// PR=3: AhBh + AhBl + AlBh (4 smem tiles/buffer).
// PR=1: AhBh only (2 smem tiles/buffer).
// KTv: k-chunk. GRAM=1: grid.z doubled; top half uses B=Bl_in, C=C2.
// ---------------------------------------------------------------------------
template <int PR, int KTv, int GRAM>
__global__ __launch_bounds__(256, 2) void tgemm_bf16(
    const __nv_bfloat16* __restrict__ Ah, const __nv_bfloat16* __restrict__ Al,
    const __nv_bfloat16* __restrict__ Bh, const __nv_bfloat16* __restrict__ Bl,
    float* __restrict__ C, float* __restrict__ C2,
    int K, int lda, int ldb, int ldc,
    long sAb, long sBb, long sCb, int nsplit, long splitStride)
{
    constexpr int STRIDEv = KTv + 8;
    constexpr int TILE = 128 * STRIDEv * 2;
    constexpr int NTILE = (PR == 1) ? 2 : 4;
    constexpr int BUF_Bv = NTILE * TILE;
    constexpr int S_AH = 0;
    constexpr int S_AL = (PR == 1) ? 0 : TILE;
    constexpr int S_BH = (PR == 1) ? TILE : 2 * TILE;
    constexpr int S_BL = (PR == 1) ? TILE : 3 * TILE;
    constexpr int SEGS = KTv / 8;

    extern __shared__ char sm[];
    const uint32_t sb = smem_u32(sm);

    const int tid = threadIdx.x;
    const int w = tid >> 5;
    const int lane = tid & 31;
    const int gid = lane >> 2;
    const int q = lane & 3;
    const int wr = w & 3;
    const int wc = w >> 2;

    int z = blockIdx.z;
    if (GRAM) {
        const int per = gridDim.z >> 1;
        if (z >= per) { z -= per; Bh = Bl; C = C2; }
    }
    const int split = z % nsplit;
    const int b = z / nsplit;
    Ah += (long)b * sAb; Al += (long)b * sAb;
    Bh += (long)b * sBb; Bl += (long)b * sBb;
    C += (long)b * sCb + (long)split * splitStride;

    const int m0 = blockIdx.y * 128;
    const int n0 = blockIdx.x * 128;
    const int Kc = K / nsplit;
    const int k0 = split * Kc;
    const int nchunks = Kc / KTv;

    float c[2][8][4];
#pragma unroll
    for (int mt = 0; mt < 2; mt++)
#pragma unroll
        for (int nt = 0; nt < 8; nt++)
#pragma unroll
            for (int i = 0; i < 4; i++) c[mt][nt][i] = 0.f;

    auto issue = [&](int ch, int buf) {
        const int kc = k0 + ch * KTv;
        const uint32_t base = sb + buf * BUF_Bv;
#pragma unroll
        for (int t = 0; t < 4; t++) {
            if (PR == 1 && (t & 1)) continue;
            const __nv_bfloat16* gp = (t == 0) ? Ah : (t == 1) ? Al : (t == 2) ? Bh : Bl;
            const int off = (t == 0) ? S_AH : (t == 1) ? S_AL : (t == 2) ? S_BH : S_BL;
            const int ld = (t < 2) ? lda : ldb;
            const int rb = (t < 2) ? m0 : n0;
#pragma unroll
            for (int p = 0; p < KTv / 16; p++) {
                const int f = p * 256 + tid;
                const int row = f / SEGS;
                const int seg = f % SEGS;
                cp_async16(base + off + (row * STRIDEv + seg * 8) * 2,
                           gp + (long)(rb + row) * ld + kc + seg * 8);
            }
        }
        asm volatile("cp.async.commit_group;" ::: "memory");
    };

    issue(0, 0);

    const int lrow = (lane & 7) + ((lane >> 3) & 1) * 8;
    const int lcol = (lane >> 4) * 8;

    for (int ch = 0; ch < nchunks; ch++) {
        const int cur = ch & 1;
        if (ch + 1 < nchunks) {
            issue(ch + 1, cur ^ 1);
            asm volatile("cp.async.wait_group 1;" ::: "memory");
        } else {
            asm volatile("cp.async.wait_group 0;" ::: "memory");
        }
        __syncthreads();

        const uint32_t base = sb + cur * BUF_Bv;
#pragma unroll
        for (int ks = 0; ks < KTv / 16; ks++) {
            const int kb = ks * 16;
#pragma unroll
            for (int pr = 0; pr < PR; pr++) {
                const uint32_t pa = base + ((pr == 2) ? S_AL : S_AH);
                const uint32_t pb = base + ((pr == 1) ? S_BL : S_BH);

                uint32_t a[2][4];
#pragma unroll
                for (int mt = 0; mt < 2; mt++) {
                    const int row = wr * 32 + mt * 16 + lrow;
                    ldm4(a[mt], pa + (row * STRIDEv + kb + lcol) * 2);
                }
#pragma unroll
                for (int ng = 0; ng < 4; ng++) {
                    const int row = wc * 64 + ng * 16 + lrow;
                    uint32_t bm[4];
                    ldm4(bm, pb + (row * STRIDEv + kb + lcol) * 2);
                    mma16816(c[0][ng * 2],     a[0], bm[0], bm[2]);
                    mma16816(c[0][ng * 2 + 1], a[0], bm[1], bm[3]);
                    mma16816(c[1][ng * 2],     a[1], bm[0], bm[2]);
                    mma16816(c[1][ng * 2 + 1], a[1], bm[1], bm[3]);
                }
            }
        }
        __syncthreads();
    }

#pragma unroll
    for (int mt = 0; mt < 2; mt++) {
        const int r = m0 + wr * 32 + mt * 16 + gid;
#pragma unroll
        for (int nt = 0; nt < 8; nt++) {
            const int col = n0 + wc * 64 + nt * 8 + q * 2;
            *(float2*)(C + (long)r * ldc + col)       = make_float2(c[mt][nt][0], c[mt][nt][1]);
            *(float2*)(C + (long)(r + 8) * ldc + col) = make_float2(c[mt][nt][2], c[mt][nt][3]);
        }
    }
}

// ---------------------------------------------------------------------------
// Small fp32 GEMM: 64x64 tile (middle chain steps 3-5)
// ---------------------------------------------------------------------------
template <int TRANSA>
__global__ __launch_bounds__(256) void gemm64(
    const float* __restrict__ A, const float* __restrict__ B, float* __restrict__ C,
    int M, int N, int K,
    int lda, int ldb, int ldc,
    long sAb, long sAh, long sBb, long sBh, long sCb, long sCh,
    int nh, int nsplit, long splitStride)
{
    int z = blockIdx.z;
    int split = z % nsplit; z /= nsplit;
    int h = z % nh;
    int b = z / nh;
    A += (long)b * sAb + (long)h * sAh;
    B += (long)b * sBb + (long)h * sBh;
    C += (long)b * sCb + (long)h * sCh + (long)split * splitStride;

    const int Kc = K / nsplit;
    const int k0 = split * Kc;

    __shared__ float As[16][64];
    __shared__ float Bs[16][64];

    const int m0 = blockIdx.y * 64;
    const int n0 = blockIdx.x * 64;
    const int tid = threadIdx.x;
    const int tx = tid & 15;
    const int ty = tid >> 4;

    float acc[4][4];
#pragma unroll
    for (int i = 0; i < 4; i++)
#pragma unroll
        for (int j = 0; j < 4; j++) acc[i][j] = 0.f;

    for (int kt = 0; kt < Kc; kt += 16) {
        if (TRANSA) {
            int k  = tid >> 4;
            int m4 = (tid & 15) * 4;
            float4 v = *reinterpret_cast<const float4*>(
                &A[(long)(k0 + kt + k) * lda + m0 + m4]);
            *reinterpret_cast<float4*>(&As[k][m4]) = v;
        } else {
            int m  = tid >> 2;
            int k4 = (tid & 3) * 4;
            float4 v = *reinterpret_cast<const float4*>(
                &A[(long)(m0 + m) * lda + (k0 + kt + k4)]);
            As[k4 + 0][m] = v.x;
            As[k4 + 1][m] = v.y;
            As[k4 + 2][m] = v.z;
            As[k4 + 3][m] = v.w;
        }
        {
            int k  = tid >> 4;
            int n4 = (tid & 15) * 4;
            float4 v = *reinterpret_cast<const float4*>(
                &B[(long)(k0 + kt + k) * ldb + n0 + n4]);
            *reinterpret_cast<float4*>(&Bs[k][n4]) = v;
        }
        __syncthreads();

#pragma unroll
        for (int k = 0; k < 16; k++) {
            float4 a = *reinterpret_cast<const float4*>(&As[k][ty * 4]);
            float4 bb = *reinterpret_cast<const float4*>(&Bs[k][tx * 4]);
            float av[4] = {a.x, a.y, a.z, a.w};
            float bv[4] = {bb.x, bb.y, bb.z, bb.w};
#pragma unroll
            for (int i = 0; i < 4; i++)
#pragma unroll
                for (int j = 0; j < 4; j++)
                    acc[i][j] += av[i] * bv[j];
        }
        __syncthreads();
    }

#pragma unroll
    for (int i = 0; i < 4; i++) {
        int m = m0 + ty * 4 + i;
        float4 v = make_float4(acc[i][0], acc[i][1], acc[i][2], acc[i][3]);
        *reinterpret_cast<float4*>(&C[(long)m * ldc + n0 + tx * 4]) = v;
    }
}

template <int P>
__global__ void reduceP(float* __restrict__ dst, const float* __restrict__ src, int n)
{
    int i = blockIdx.x * 256 + threadIdx.x;
    if (i < n) {
        float s = 0.f;
#pragma unroll
        for (int p = 0; p < P; p++) s += src[(long)p * n + i];
        dst[i] = s;
    }
}

// ---------------------------------------------------------------------------
extern "C" void kernel_launch(void* const* d_in, const int* in_sizes, int n_in,
                              void* d_out, int out_size)
{
    const float* x  = (const float*)d_in[0];
    const float* Wq = (const float*)d_in[1];
    const float* Wk = (const float*)d_in[2];
    const float* Wv = (const float*)d_in[3];
    const float* Wo = (const float*)d_in[4];
    float* out = (float*)d_out;

    float *Gp1, *Gp2, *P, *Mp, *M2, *T2;
    cudaGetSymbolAddress((void**)&Gp1, g_Gp1);
    cudaGetSymbolAddress((void**)&Gp2, g_Gp2);
    cudaGetSymbolAddress((void**)&P,   g_P);
    cudaGetSymbolAddress((void**)&Mp,  g_Mpart);
    cudaGetSymbolAddress((void**)&M2,  g_M2);
    cudaGetSymbolAddress((void**)&T2,  g_T2);

    __nv_bfloat16 *xh, *xl, *xTh, *xTl, *FTh, *FTl, *Gh, *Gl, *WkTh, *WkTl;
    cudaGetSymbolAddress((void**)&xh,   g_xh);
    cudaGetSymbolAddress((void**)&xl,   g_xl);
    cudaGetSymbolAddress((void**)&xTh,  g_xTh);
    cudaGetSymbolAddress((void**)&xTl,  g_xTl);
    cudaGetSymbolAddress((void**)&FTh,  g_FTh);
    cudaGetSymbolAddress((void**)&FTl,  g_FTl);
    cudaGetSymbolAddress((void**)&Gh,   g_Gh);
    cudaGetSymbolAddress((void**)&Gl,   g_Gl);
    cudaGetSymbolAddress((void**)&WkTh, g_WkTh);
    cudaGetSymbolAddress((void**)&WkTl, g_WkTl);

    const int TG1_SMEM = 2 * 2 * (128 * 72 * 2);   // KT=64, PR=1: 73728
    const int TG3_SMEM = 2 * 4 * (128 * 40 * 2);   // KT=32, PR=3: 81920
    cudaFuncSetAttribute((const void*)tgemm_bf16<1, 64, 1>,
                         cudaFuncAttributeMaxDynamicSharedMemorySize, TG1_SMEM);
    cudaFuncSetAttribute((const void*)tgemm_bf16<3, 32, 0>,
                         cudaFuncAttributeMaxDynamicSharedMemorySize, TG3_SMEM);

    const long LD   = (long)LL * DIN;
    const long GS   = (long)DIN * DIN;
    const long WKS  = (long)DIN * DK;
    const long PSH  = (long)DK * DIN;
    const long PSB  = (long)HH * PSH;
    const long MSH  = (long)DK * DV;
    const long MSB  = (long)HH * MSH;
    const long XTS  = (long)DIN * LL;

    // 0) split x; prep WkT
    split_x_kernel<<<dim3(DIN / 32, LL / 32, BB), dim3(32, 8)>>>(x, xh, xl, xTh, xTl);
    prep_WkT_kernel<<<dim3(DK / 32, DIN / 32, HH), dim3(32, 8)>>>(Wk, WkTh, WkTl);

    // 1) Gram, both symmetric products, ONE launch, split-K=4 -> 256 CTAs (1 wave)
    tgemm_bf16<1, 64, 1><<<dim3(4, 4, BB * 4 * 2), 256, TG1_SMEM>>>(
        xTh, xTh, xTh, xTl, Gp1, Gp2,
        LL, LL, LL, DIN, XTS, XTS, GS, 4, (long)BB * GS);
    reduceG_kernel<<<dim3(16, 16, BB), dim3(32, 8)>>>(Gp1, Gp2, Gh, Gl);

    // 2) P_all[b] = WkT_flat @ G[b]  (split-K=4 -> grid 128; partials reuse Gp1)
    tgemm_bf16<3, 32, 0><<<dim3(4, 4, BB * 4), 256, TG3_SMEM>>>(
        WkTh, WkTl, Gh, Gl, Gp1, Gp1,
        DIN, DIN, DIN, DIN, 0, GS, GS, 4, (long)BB * GS);
    reduceP<4><<<(int)((BB * GS + 255) / 256), 256>>>(P, Gp1, BB * GS);

    // 3) M[b,h] = P[b,h] @ Wv[h]  (64x64, K=512), split-K=8 -> 128 CTAs
    gemm64<0><<<dim3(1, 1, BB * HH * 8), 256>>>(
        P, Wv, Mp, DK, DV, DIN,
        DIN, DV, DV,
        PSB, PSH, 0, WKS, MSB, MSH,
        HH, 8, (long)BB * HH * DK * DV);
    reduceP<8><<<(BB * HH * DK * DV + 255) / 256, 256>>>(M2, Mp, BB * HH * DK * DV);

    // 4) T2cat[b][:, h*64:] = Wq[h] @ M[b,h]  (512x64, K=64), 128 CTAs
    gemm64<0><<<dim3(1, 8, BB * HH), 256>>>(
        Wq, M2, T2, DIN, DV, DK,
        DK, DV, HH * DV,
        0, WKS, MSB, MSH, (long)DIN * HH * DV, (long)DV,
        HH, 1, 0);

    // 5) F partials = T2cat[b] @ Wo_flat  (split-K=4 -> 256 CTAs; partials in Gp2)
    gemm64<0><<<dim3(8, 8, BB * 4), 256>>>(
        T2, Wo, Gp2, DIN, DOUT, HH * DV,
        HH * DV, DOUT, DOUT,
        (long)DIN * HH * DV, 0, 0, 0, (long)DIN * DOUT, 0,
        1, 4, (long)BB * DIN * DOUT);

    // 5b) fused: F = sum partials; FT bf16 hi/lo (transposed) in one pass
    reduceF_splitFT_kernel<<<dim3(DOUT / 32, DIN / 32, BB), dim3(32, 8)>>>(Gp2, FTh, FTl);

    // 6) out[b] = x[b] @ F[b]  (tensor, 3-product), 256 CTAs
    tgemm_bf16<3, 32, 0><<<dim3(4, 32, BB), 256, TG3_SMEM>>>(
        xh, xl, FTh, FTl, out, out,
        DIN, DIN, DIN, DOUT,
        LD, (long)DOUT * DIN, (long)LL * DOUT, 1, 0);
}